// round 2
// baseline (speedup 1.0000x reference)
#include <cuda_runtime.h>
#include <cuda_bf16.h>
#include <cstdint>

#define N_ROWS 4096
#define CIN 128

// ---------------- device scratch (no allocation allowed) ----------------
__device__ float g_v[4][128];        // v1_irr, v2_irr, v1_sol, v2_sol
__device__ float g_c[4];             // score constants
__device__ float g_bias[128];        // Wi_b0+Wi_b1+Ws_b0+Ws_b1+Wh_b
__device__ float g_s[4][N_ROWS];     // s1_irr, s2_irr, s1_sol, s2_sol
__device__ float g_Ldx[N_ROWS * 128];
__device__ float g_Lux[N_ROWS * 128];
__device__ float g_Px[2 * N_ROWS * 128];   // split-K partials
__device__ float g_Mirr[N_ROWS * 128];
__device__ float g_Msol[N_ROWS * 128];
__device__ float g_rowmax[2][N_ROWS];

// ---------------- kernel 1: fold attention vectors + biases ----------------
__global__ void k_prep(const float* __restrict__ Wi_w, const float* __restrict__ Wi_b,
                       const float* __restrict__ Ws_w, const float* __restrict__ Ws_b,
                       const float* __restrict__ Wh_b,
                       const float* __restrict__ att_irr, const float* __restrict__ att_sol) {
    int c = threadIdx.x;  // 0..127
    float v1i = 0.f, v2i = 0.f, v1s = 0.f, v2s = 0.f;
    for (int j = 0; j < 2; j++) {
        for (int o = 0; o < 128; o++) {
            int a = j * 128 + o;
            float wi = Wi_w[(j * 128 + c) * 128 + o];
            float ws = Ws_w[(j * 128 + c) * 128 + o];
            v1i += wi * att_irr[a];       v2i += wi * att_irr[256 + a];
            v1s += ws * att_sol[a];       v2s += ws * att_sol[256 + a];
        }
    }
    g_v[0][c] = v1i; g_v[1][c] = v2i; g_v[2][c] = v1s; g_v[3][c] = v2s;

    float c1i = 0.f, c2i = 0.f, c1s = 0.f, c2s = 0.f;
    for (int j = 0; j < 2; j++) {
        int a = j * 128 + c;
        c1i += Wi_b[a] * att_irr[a];  c2i += Wi_b[a] * att_irr[256 + a];
        c1s += Ws_b[a] * att_sol[a];  c2s += Ws_b[a] * att_sol[256 + a];
    }
    __shared__ float red[4][128];
    red[0][c] = c1i; red[1][c] = c2i; red[2][c] = c1s; red[3][c] = c2s;
    __syncthreads();
    for (int s = 64; s > 0; s >>= 1) {
        if (c < s) {
            for (int q = 0; q < 4; q++) red[q][c] += red[q][c + s];
        }
        __syncthreads();
    }
    if (c < 4) g_c[c] = red[c][0];
    g_bias[c] = Wi_b[c] + Wi_b[128 + c] + Ws_b[c] + Ws_b[128 + c] + Wh_b[c];
}

// ---------------- kernel 2: per-node scores s = x @ v + c ----------------
__global__ void k_scores(const float* __restrict__ x) {
    int i = blockIdx.x, t = threadIdx.x;
    float xv = x[(size_t)i * 128 + t];
    __shared__ float red[4][128];
    red[0][t] = xv * g_v[0][t];
    red[1][t] = xv * g_v[1][t];
    red[2][t] = xv * g_v[2][t];
    red[3][t] = xv * g_v[3][t];
    __syncthreads();
    for (int s = 64; s > 0; s >>= 1) {
        if (t < s) {
            for (int q = 0; q < 4; q++) red[q][t] += red[q][t + s];
        }
        __syncthreads();
    }
    if (t < 4) g_s[t][i] = red[t][0] + g_c[t];
}

// ---------------- kernel 3: sparse L@x + row max of masked leaky scores ----------------
__global__ __launch_bounds__(128) void k_spmm(const float* __restrict__ L, const float* __restrict__ x,
                                              const float* __restrict__ s1, const float* __restrict__ s2,
                                              float* __restrict__ Lx, float* __restrict__ rowmax) {
    int i = blockIdx.x, t = threadIdx.x;
    float s1i = s1[i];
    float acc = 0.f, mmax = -INFINITY;
    __shared__ int s_idx[128];
    __shared__ float s_val[128];
    __shared__ int s_cnt;
    for (int j0 = 0; j0 < N_ROWS; j0 += 128) {
        if (t == 0) s_cnt = 0;
        __syncthreads();
        float lv = L[(size_t)i * N_ROWS + j0 + t];
        if (lv != 0.f) {
            float e = s1i + s2[j0 + t];
            e = (e >= 0.f) ? e : 0.2f * e;
            mmax = fmaxf(mmax, e);
            int p = atomicAdd(&s_cnt, 1);
            s_idx[p] = j0 + t;
            s_val[p] = lv;
        }
        __syncthreads();
        int c = s_cnt;
        for (int p = 0; p < c; p++) acc += s_val[p] * x[(size_t)s_idx[p] * 128 + t];
        __syncthreads();
    }
    Lx[(size_t)i * 128 + t] = acc;
    __shared__ float rmx[128];
    rmx[t] = mmax;
    __syncthreads();
    for (int s = 64; s > 0; s >>= 1) {
        if (t < s) rmx[t] = fmaxf(rmx[t], rmx[t + s]);
        __syncthreads();
    }
    if (t == 0) rowmax[i] = rmx[0];
}

// ---------------- kernel 4: dense P@x, SIMT fp32, split-K=2 ----------------
__global__ __launch_bounds__(256) void k_gemm_px(const float* __restrict__ A, const float* __restrict__ B,
                                                 float* __restrict__ C) {
    __shared__ float As[32][65];   // [k][m], padded conflict-free
    __shared__ float Bs[32][128];
    int tid = threadIdx.x;
    int bm = blockIdx.x * 64;
    int kbeg = blockIdx.y * 2048;
    int trow = (tid >> 5) * 8;
    int tcol = (tid & 31) * 4;
    int am = tid >> 3;            // 0..31 (rows am and am+32)
    int ak = (tid & 7) * 4;
    int br = tid >> 5;            // 0..7
    int bc = (tid & 31) * 4;
    float acc[8][4];
#pragma unroll
    for (int r = 0; r < 8; r++)
#pragma unroll
        for (int c = 0; c < 4; c++) acc[r][c] = 0.f;

    for (int kk = kbeg; kk < kbeg + 2048; kk += 32) {
        float4 av0 = *(const float4*)&A[(size_t)(bm + am) * N_ROWS + kk + ak];
        float4 av1 = *(const float4*)&A[(size_t)(bm + am + 32) * N_ROWS + kk + ak];
        As[ak + 0][am] = av0.x; As[ak + 1][am] = av0.y; As[ak + 2][am] = av0.z; As[ak + 3][am] = av0.w;
        As[ak + 0][am + 32] = av1.x; As[ak + 1][am + 32] = av1.y; As[ak + 2][am + 32] = av1.z; As[ak + 3][am + 32] = av1.w;
#pragma unroll
        for (int q = 0; q < 4; q++)
            *(float4*)&Bs[br + q * 8][bc] = *(const float4*)&B[(size_t)(kk + br + q * 8) * 128 + bc];
        __syncthreads();
#pragma unroll
        for (int k = 0; k < 32; k++) {
            float a[8];
#pragma unroll
            for (int r = 0; r < 8; r++) a[r] = As[k][trow + r];
            float4 bv = *(float4*)&Bs[k][tcol];
#pragma unroll
            for (int r = 0; r < 8; r++) {
                acc[r][0] += a[r] * bv.x;
                acc[r][1] += a[r] * bv.y;
                acc[r][2] += a[r] * bv.z;
                acc[r][3] += a[r] * bv.w;
            }
        }
        __syncthreads();
    }
    float* Cs = C + (size_t)blockIdx.y * N_ROWS * 128;
#pragma unroll
    for (int r = 0; r < 8; r++) {
        float4 o = make_float4(acc[r][0], acc[r][1], acc[r][2], acc[r][3]);
        *(float4*)&Cs[(size_t)(bm + trow + r) * 128 + tcol] = o;
    }
}

// ---------------- kernel 5: C = A1@W1 + A2@W2 (+bias), K=128 ----------------
template <bool ADD_BIAS>
__global__ __launch_bounds__(256) void k_gemm2(const float* __restrict__ A1, const float* __restrict__ A2,
                                               const float* __restrict__ W1, const float* __restrict__ W2,
                                               float* __restrict__ C) {
    __shared__ float A1s[32][33];
    __shared__ float A2s[32][33];
    __shared__ float W1s[32][128];
    __shared__ float W2s[32][128];
    int tid = threadIdx.x;
    int bm = blockIdx.x * 32;
    int trow = (tid >> 5) * 4;
    int tcol = (tid & 31) * 4;
    int am = tid >> 3;          // 0..31
    int ak = (tid & 7) * 4;
    int wr = tid >> 5;          // 0..7
    int wc = (tid & 31) * 4;
    float acc[4][4];
#pragma unroll
    for (int r = 0; r < 4; r++)
#pragma unroll
        for (int c = 0; c < 4; c++) acc[r][c] = 0.f;

    for (int kk = 0; kk < 128; kk += 32) {
        float4 a1 = *(const float4*)&A1[(size_t)(bm + am) * 128 + kk + ak];
        float4 a2 = *(const float4*)&A2[(size_t)(bm + am) * 128 + kk + ak];
        A1s[ak + 0][am] = a1.x; A1s[ak + 1][am] = a1.y; A1s[ak + 2][am] = a1.z; A1s[ak + 3][am] = a1.w;
        A2s[ak + 0][am] = a2.x; A2s[ak + 1][am] = a2.y; A2s[ak + 2][am] = a2.z; A2s[ak + 3][am] = a2.w;
#pragma unroll
        for (int q = 0; q < 4; q++) {
            *(float4*)&W1s[wr + q * 8][wc] = *(const float4*)&W1[(size_t)(kk + wr + q * 8) * 128 + wc];
            *(float4*)&W2s[wr + q * 8][wc] = *(const float4*)&W2[(size_t)(kk + wr + q * 8) * 128 + wc];
        }
        __syncthreads();
#pragma unroll
        for (int k = 0; k < 32; k++) {
            float a1f[4], a2f[4];
#pragma unroll
            for (int r = 0; r < 4; r++) { a1f[r] = A1s[k][trow + r]; a2f[r] = A2s[k][trow + r]; }
            float4 w1v = *(float4*)&W1s[k][tcol];
            float4 w2v = *(float4*)&W2s[k][tcol];
#pragma unroll
            for (int r = 0; r < 4; r++) {
                acc[r][0] += a1f[r] * w1v.x + a2f[r] * w2v.x;
                acc[r][1] += a1f[r] * w1v.y + a2f[r] * w2v.y;
                acc[r][2] += a1f[r] * w1v.z + a2f[r] * w2v.z;
                acc[r][3] += a1f[r] * w1v.w + a2f[r] * w2v.w;
            }
        }
        __syncthreads();
    }
#pragma unroll
    for (int r = 0; r < 4; r++) {
        float4 o = make_float4(acc[r][0], acc[r][1], acc[r][2], acc[r][3]);
        if (ADD_BIAS) {
            o.x += g_bias[tcol + 0];
            o.y += g_bias[tcol + 1];
            o.z += g_bias[tcol + 2];
            o.w += g_bias[tcol + 3];
        }
        *(float4*)&C[(size_t)(bm + trow + r) * 128 + tcol] = o;
    }
}

// ---------------- kernel 6: z += softmax_row(mask(leaky(s1+s2))) @ M ----------------
__global__ __launch_bounds__(128) void k_attn(const float* __restrict__ L, const float* __restrict__ M,
                                              const float* __restrict__ s1, const float* __restrict__ s2,
                                              const float* __restrict__ rowmax, float* __restrict__ z) {
    int i = blockIdx.x, t = threadIdx.x;
    float s1i = s1[i];
    float m = rowmax[i];
    bool allm = !(m > -1e30f);  // entire row masked -> uniform softmax
    float acc = 0.f, dpart = 0.f;
    __shared__ int s_idx[128];
    __shared__ float s_w[128];
    __shared__ int s_cnt;
    for (int j0 = 0; j0 < N_ROWS; j0 += 128) {
        if (t == 0) s_cnt = 0;
        __syncthreads();
        float lv = L[(size_t)i * N_ROWS + j0 + t];
        float w = 0.f;
        if (allm) {
            w = 1.f;
        } else if (lv != 0.f) {
            float e = s1i + s2[j0 + t];
            e = (e >= 0.f) ? e : 0.2f * e;
            w = __expf(e - m);
        }
        if (w != 0.f) {
            dpart += w;
            int p = atomicAdd(&s_cnt, 1);
            s_idx[p] = j0 + t;
            s_w[p] = w;
        }
        __syncthreads();
        int c = s_cnt;
        for (int p = 0; p < c; p++) acc += s_w[p] * M[(size_t)s_idx[p] * 128 + t];
        __syncthreads();
    }
    __shared__ float red[128];
    red[t] = dpart;
    __syncthreads();
    for (int s = 64; s > 0; s >>= 1) {
        if (t < s) red[t] += red[t + s];
        __syncthreads();
    }
    float d = red[0];
    z[(size_t)i * 128 + t] += acc / d;
}

// ---------------- host launcher ----------------
extern "C" void kernel_launch(void* const* d_in, const int* in_sizes, int n_in,
                              void* d_out, int out_size) {
    const float* x       = (const float*)d_in[0];
    const float* Lu      = (const float*)d_in[1];
    const float* Ld      = (const float*)d_in[2];
    const float* P       = (const float*)d_in[3];
    const float* Wi_w    = (const float*)d_in[4];
    const float* Wi_b    = (const float*)d_in[5];
    const float* Ws_w    = (const float*)d_in[6];
    const float* Ws_b    = (const float*)d_in[7];
    const float* Wh_w    = (const float*)d_in[8];
    const float* Wh_b    = (const float*)d_in[9];
    const float* att_irr = (const float*)d_in[10];
    const float* att_sol = (const float*)d_in[11];
    float* z = (float*)d_out;

    float *p_s, *p_Ldx, *p_Lux, *p_Px, *p_Mirr, *p_Msol, *p_rowmax;
    cudaGetSymbolAddress((void**)&p_s, g_s);
    cudaGetSymbolAddress((void**)&p_Ldx, g_Ldx);
    cudaGetSymbolAddress((void**)&p_Lux, g_Lux);
    cudaGetSymbolAddress((void**)&p_Px, g_Px);
    cudaGetSymbolAddress((void**)&p_Mirr, g_Mirr);
    cudaGetSymbolAddress((void**)&p_Msol, g_Msol);
    cudaGetSymbolAddress((void**)&p_rowmax, g_rowmax);

    k_prep<<<1, 128>>>(Wi_w, Wi_b, Ws_w, Ws_b, Wh_b, att_irr, att_sol);
    k_scores<<<N_ROWS, 128>>>(x);

    // sparse Laplacian*x + attention row maxes
    k_spmm<<<N_ROWS, 128>>>(Ld, x, p_s + 0 * N_ROWS, p_s + 1 * N_ROWS, p_Ldx, p_rowmax);
    k_spmm<<<N_ROWS, 128>>>(Lu, x, p_s + 2 * N_ROWS, p_s + 3 * N_ROWS, p_Lux, p_rowmax + N_ROWS);

    // dense P @ x (split-K = 2)
    k_gemm_px<<<dim3(N_ROWS / 64, 2), 256>>>(P, x, p_Px);

    // M_irr = x@Wi0 + (Ld@x)@Wi1 ;  M_sol = x@Ws0 + (Lu@x)@Ws1
    k_gemm2<false><<<N_ROWS / 32, 256>>>(x, p_Ldx, Wi_w, Wi_w + 128 * 128, p_Mirr);
    k_gemm2<false><<<N_ROWS / 32, 256>>>(x, p_Lux, Ws_w, Ws_w + 128 * 128, p_Msol);
    // z = (Px0 + Px1)@Wh + total_bias   (same W applied to both split-K slabs)
    k_gemm2<true><<<N_ROWS / 32, 256>>>(p_Px, p_Px + N_ROWS * 128, Wh_w, Wh_w, z);

    // z += softmax(Ld-masked) @ M_irr ;  z += softmax(Lu-masked) @ M_sol
    k_attn<<<N_ROWS, 128>>>(Ld, p_Mirr, p_s + 0 * N_ROWS, p_s + 1 * N_ROWS, p_rowmax, z);
    k_attn<<<N_ROWS, 128>>>(Lu, p_Msol, p_s + 2 * N_ROWS, p_s + 3 * N_ROWS, p_rowmax + N_ROWS, z);
}

// round 3
// speedup vs baseline: 1.0092x; 1.0092x over previous
#include <cuda_runtime.h>
#include <cuda_bf16.h>
#include <cstdint>

#define N_ROWS 4096
#define CIN 128

// ---------------- device scratch (no allocation allowed) ----------------
__device__ float g_v[4][128];        // v1_irr, v2_irr, v1_sol, v2_sol
__device__ float g_c[4];             // score constants
__device__ float g_bias[128];        // Wi_b0+Wi_b1+Ws_b0+Ws_b1+Wh_b
__device__ float g_s[4][N_ROWS];     // s1_irr, s2_irr, s1_sol, s2_sol
__device__ float g_Ldx[N_ROWS * 128];
__device__ float g_Lux[N_ROWS * 128];
__device__ float g_Px[2 * N_ROWS * 128];   // split-K partials
__device__ float g_Mirr[N_ROWS * 128];
__device__ float g_Msol[N_ROWS * 128];
__device__ float g_rowmax[2][N_ROWS];

// ---------------- kernel 1: fold attention vectors + biases ----------------
__global__ void k_prep(const float* __restrict__ Wi_w, const float* __restrict__ Wi_b,
                       const float* __restrict__ Ws_w, const float* __restrict__ Ws_b,
                       const float* __restrict__ Wh_b,
                       const float* __restrict__ att_irr, const float* __restrict__ att_sol) {
    int c = threadIdx.x;  // 0..127
    float v1i = 0.f, v2i = 0.f, v1s = 0.f, v2s = 0.f;
    for (int j = 0; j < 2; j++) {
        for (int o = 0; o < 128; o++) {
            int a = j * 128 + o;
            float wi = Wi_w[(j * 128 + c) * 128 + o];
            float ws = Ws_w[(j * 128 + c) * 128 + o];
            v1i += wi * att_irr[a];       v2i += wi * att_irr[256 + a];
            v1s += ws * att_sol[a];       v2s += ws * att_sol[256 + a];
        }
    }
    g_v[0][c] = v1i; g_v[1][c] = v2i; g_v[2][c] = v1s; g_v[3][c] = v2s;

    float c1i = 0.f, c2i = 0.f, c1s = 0.f, c2s = 0.f;
    for (int j = 0; j < 2; j++) {
        int a = j * 128 + c;
        c1i += Wi_b[a] * att_irr[a];  c2i += Wi_b[a] * att_irr[256 + a];
        c1s += Ws_b[a] * att_sol[a];  c2s += Ws_b[a] * att_sol[256 + a];
    }
    __shared__ float red[4][128];
    red[0][c] = c1i; red[1][c] = c2i; red[2][c] = c1s; red[3][c] = c2s;
    __syncthreads();
    for (int s = 64; s > 0; s >>= 1) {
        if (c < s) {
            for (int q = 0; q < 4; q++) red[q][c] += red[q][c + s];
        }
        __syncthreads();
    }
    if (c < 4) g_c[c] = red[c][0];
    g_bias[c] = Wi_b[c] + Wi_b[128 + c] + Ws_b[c] + Ws_b[128 + c] + Wh_b[c];
}

// ---------------- kernel 2: per-node scores s = x @ v + c ----------------
__global__ void k_scores(const float* __restrict__ x) {
    int i = blockIdx.x, t = threadIdx.x;
    float xv = x[(size_t)i * 128 + t];
    __shared__ float red[4][128];
    red[0][t] = xv * g_v[0][t];
    red[1][t] = xv * g_v[1][t];
    red[2][t] = xv * g_v[2][t];
    red[3][t] = xv * g_v[3][t];
    __syncthreads();
    for (int s = 64; s > 0; s >>= 1) {
        if (t < s) {
            for (int q = 0; q < 4; q++) red[q][t] += red[q][t + s];
        }
        __syncthreads();
    }
    if (t < 4) g_s[t][i] = red[t][0] + g_c[t];
}

// ---------------- kernel 3: sparse L@x + row max of masked leaky scores ----------------
__global__ __launch_bounds__(128) void k_spmm(const float* __restrict__ L, const float* __restrict__ x,
                                              const float* __restrict__ s1, const float* __restrict__ s2,
                                              float* __restrict__ Lx, float* __restrict__ rowmax) {
    int i = blockIdx.x, t = threadIdx.x;
    float s1i = s1[i];
    float acc = 0.f, mmax = -INFINITY;
    __shared__ int s_idx[128];
    __shared__ float s_val[128];
    __shared__ int s_cnt;
    for (int j0 = 0; j0 < N_ROWS; j0 += 128) {
        if (t == 0) s_cnt = 0;
        __syncthreads();
        float lv = L[(size_t)i * N_ROWS + j0 + t];
        if (lv != 0.f) {
            float e = s1i + s2[j0 + t];
            e = (e >= 0.f) ? e : 0.2f * e;
            mmax = fmaxf(mmax, e);
            int p = atomicAdd(&s_cnt, 1);
            s_idx[p] = j0 + t;
            s_val[p] = lv;
        }
        __syncthreads();
        int c = s_cnt;
        for (int p = 0; p < c; p++) acc += s_val[p] * x[(size_t)s_idx[p] * 128 + t];
        __syncthreads();
    }
    Lx[(size_t)i * 128 + t] = acc;
    __shared__ float rmx[128];
    rmx[t] = mmax;
    __syncthreads();
    for (int s = 64; s > 0; s >>= 1) {
        if (t < s) rmx[t] = fmaxf(rmx[t], rmx[t + s]);
        __syncthreads();
    }
    if (t == 0) rowmax[i] = rmx[0];
}

// ---------------- kernel 4: dense P@x, SIMT fp32, split-K=2 ----------------
__global__ __launch_bounds__(256) void k_gemm_px(const float* __restrict__ A, const float* __restrict__ B,
                                                 float* __restrict__ C) {
    __shared__ float As[32][65];   // [k][m], padded conflict-free
    __shared__ float Bs[32][128];
    int tid = threadIdx.x;
    int bm = blockIdx.x * 64;
    int kbeg = blockIdx.y * 2048;
    int trow = (tid >> 5) * 8;
    int tcol = (tid & 31) * 4;
    int am = tid >> 3;            // 0..31 (rows am and am+32)
    int ak = (tid & 7) * 4;
    int br = tid >> 5;            // 0..7
    int bc = (tid & 31) * 4;
    float acc[8][4];
#pragma unroll
    for (int r = 0; r < 8; r++)
#pragma unroll
        for (int c = 0; c < 4; c++) acc[r][c] = 0.f;

    for (int kk = kbeg; kk < kbeg + 2048; kk += 32) {
        float4 av0 = *(const float4*)&A[(size_t)(bm + am) * N_ROWS + kk + ak];
        float4 av1 = *(const float4*)&A[(size_t)(bm + am + 32) * N_ROWS + kk + ak];
        As[ak + 0][am] = av0.x; As[ak + 1][am] = av0.y; As[ak + 2][am] = av0.z; As[ak + 3][am] = av0.w;
        As[ak + 0][am + 32] = av1.x; As[ak + 1][am + 32] = av1.y; As[ak + 2][am + 32] = av1.z; As[ak + 3][am + 32] = av1.w;
#pragma unroll
        for (int q = 0; q < 4; q++)
            *(float4*)&Bs[br + q * 8][bc] = *(const float4*)&B[(size_t)(kk + br + q * 8) * 128 + bc];
        __syncthreads();
#pragma unroll
        for (int k = 0; k < 32; k++) {
            float a[8];
#pragma unroll
            for (int r = 0; r < 8; r++) a[r] = As[k][trow + r];
            float4 bv = *(float4*)&Bs[k][tcol];
#pragma unroll
            for (int r = 0; r < 8; r++) {
                acc[r][0] += a[r] * bv.x;
                acc[r][1] += a[r] * bv.y;
                acc[r][2] += a[r] * bv.z;
                acc[r][3] += a[r] * bv.w;
            }
        }
        __syncthreads();
    }
    float* Cs = C + (size_t)blockIdx.y * N_ROWS * 128;
#pragma unroll
    for (int r = 0; r < 8; r++) {
        float4 o = make_float4(acc[r][0], acc[r][1], acc[r][2], acc[r][3]);
        *(float4*)&Cs[(size_t)(bm + trow + r) * 128 + tcol] = o;
    }
}

// ---------------- kernel 5: C = A1@W1 + A2@W2 (+bias), K=128 ----------------
template <bool ADD_BIAS>
__global__ __launch_bounds__(256) void k_gemm2(const float* __restrict__ A1, const float* __restrict__ A2,
                                               const float* __restrict__ W1, const float* __restrict__ W2,
                                               float* __restrict__ C) {
    __shared__ float A1s[32][33];
    __shared__ float A2s[32][33];
    __shared__ float W1s[32][128];
    __shared__ float W2s[32][128];
    int tid = threadIdx.x;
    int bm = blockIdx.x * 32;
    int trow = (tid >> 5) * 4;
    int tcol = (tid & 31) * 4;
    int am = tid >> 3;          // 0..31
    int ak = (tid & 7) * 4;
    int wr = tid >> 5;          // 0..7
    int wc = (tid & 31) * 4;
    float acc[4][4];
#pragma unroll
    for (int r = 0; r < 4; r++)
#pragma unroll
        for (int c = 0; c < 4; c++) acc[r][c] = 0.f;

    for (int kk = 0; kk < 128; kk += 32) {
        float4 a1 = *(const float4*)&A1[(size_t)(bm + am) * 128 + kk + ak];
        float4 a2 = *(const float4*)&A2[(size_t)(bm + am) * 128 + kk + ak];
        A1s[ak + 0][am] = a1.x; A1s[ak + 1][am] = a1.y; A1s[ak + 2][am] = a1.z; A1s[ak + 3][am] = a1.w;
        A2s[ak + 0][am] = a2.x; A2s[ak + 1][am] = a2.y; A2s[ak + 2][am] = a2.z; A2s[ak + 3][am] = a2.w;
#pragma unroll
        for (int q = 0; q < 4; q++) {
            *(float4*)&W1s[wr + q * 8][wc] = *(const float4*)&W1[(size_t)(kk + wr + q * 8) * 128 + wc];
            *(float4*)&W2s[wr + q * 8][wc] = *(const float4*)&W2[(size_t)(kk + wr + q * 8) * 128 + wc];
        }
        __syncthreads();
#pragma unroll
        for (int k = 0; k < 32; k++) {
            float a1f[4], a2f[4];
#pragma unroll
            for (int r = 0; r < 4; r++) { a1f[r] = A1s[k][trow + r]; a2f[r] = A2s[k][trow + r]; }
            float4 w1v = *(float4*)&W1s[k][tcol];
            float4 w2v = *(float4*)&W2s[k][tcol];
#pragma unroll
            for (int r = 0; r < 4; r++) {
                acc[r][0] += a1f[r] * w1v.x + a2f[r] * w2v.x;
                acc[r][1] += a1f[r] * w1v.y + a2f[r] * w2v.y;
                acc[r][2] += a1f[r] * w1v.z + a2f[r] * w2v.z;
                acc[r][3] += a1f[r] * w1v.w + a2f[r] * w2v.w;
            }
        }
        __syncthreads();
    }
#pragma unroll
    for (int r = 0; r < 4; r++) {
        float4 o = make_float4(acc[r][0], acc[r][1], acc[r][2], acc[r][3]);
        if (ADD_BIAS) {
            o.x += g_bias[tcol + 0];
            o.y += g_bias[tcol + 1];
            o.z += g_bias[tcol + 2];
            o.w += g_bias[tcol + 3];
        }
        *(float4*)&C[(size_t)(bm + trow + r) * 128 + tcol] = o;
    }
}

// ---------------- kernel 6: z += softmax_row(mask(leaky(s1+s2))) @ M ----------------
__global__ __launch_bounds__(128) void k_attn(const float* __restrict__ L, const float* __restrict__ M,
                                              const float* __restrict__ s1, const float* __restrict__ s2,
                                              const float* __restrict__ rowmax, float* __restrict__ z) {
    int i = blockIdx.x, t = threadIdx.x;
    float s1i = s1[i];
    float m = rowmax[i];
    bool allm = !(m > -1e30f);  // entire row masked -> uniform softmax
    float acc = 0.f, dpart = 0.f;
    __shared__ int s_idx[128];
    __shared__ float s_w[128];
    __shared__ int s_cnt;
    for (int j0 = 0; j0 < N_ROWS; j0 += 128) {
        if (t == 0) s_cnt = 0;
        __syncthreads();
        float lv = L[(size_t)i * N_ROWS + j0 + t];
        float w = 0.f;
        if (allm) {
            w = 1.f;
        } else if (lv != 0.f) {
            float e = s1i + s2[j0 + t];
            e = (e >= 0.f) ? e : 0.2f * e;
            w = __expf(e - m);
        }
        if (w != 0.f) {
            dpart += w;
            int p = atomicAdd(&s_cnt, 1);
            s_idx[p] = j0 + t;
            s_w[p] = w;
        }
        __syncthreads();
        int c = s_cnt;
        for (int p = 0; p < c; p++) acc += s_w[p] * M[(size_t)s_idx[p] * 128 + t];
        __syncthreads();
    }
    __shared__ float red[128];
    red[t] = dpart;
    __syncthreads();
    for (int s = 64; s > 0; s >>= 1) {
        if (t < s) red[t] += red[t + s];
        __syncthreads();
    }
    float d = red[0];
    z[(size_t)i * 128 + t] += acc / d;
}

// ---------------- host launcher ----------------
extern "C" void kernel_launch(void* const* d_in, const int* in_sizes, int n_in,
                              void* d_out, int out_size) {
    const float* x       = (const float*)d_in[0];
    const float* Lu      = (const float*)d_in[1];
    const float* Ld      = (const float*)d_in[2];
    const float* P       = (const float*)d_in[3];
    const float* Wi_w    = (const float*)d_in[4];
    const float* Wi_b    = (const float*)d_in[5];
    const float* Ws_w    = (const float*)d_in[6];
    const float* Ws_b    = (const float*)d_in[7];
    const float* Wh_w    = (const float*)d_in[8];
    const float* Wh_b    = (const float*)d_in[9];
    const float* att_irr = (const float*)d_in[10];
    const float* att_sol = (const float*)d_in[11];
    float* z = (float*)d_out;

    float *p_s, *p_Ldx, *p_Lux, *p_Px, *p_Mirr, *p_Msol, *p_rowmax;
    cudaGetSymbolAddress((void**)&p_s, g_s);
    cudaGetSymbolAddress((void**)&p_Ldx, g_Ldx);
    cudaGetSymbolAddress((void**)&p_Lux, g_Lux);
    cudaGetSymbolAddress((void**)&p_Px, g_Px);
    cudaGetSymbolAddress((void**)&p_Mirr, g_Mirr);
    cudaGetSymbolAddress((void**)&p_Msol, g_Msol);
    cudaGetSymbolAddress((void**)&p_rowmax, g_rowmax);

    k_prep<<<1, 128>>>(Wi_w, Wi_b, Ws_w, Ws_b, Wh_b, att_irr, att_sol);
    k_scores<<<N_ROWS, 128>>>(x);

    // sparse Laplacian*x + attention row maxes
    k_spmm<<<N_ROWS, 128>>>(Ld, x, p_s + 0 * N_ROWS, p_s + 1 * N_ROWS, p_Ldx, p_rowmax);
    k_spmm<<<N_ROWS, 128>>>(Lu, x, p_s + 2 * N_ROWS, p_s + 3 * N_ROWS, p_Lux, p_rowmax + N_ROWS);

    // dense P @ x (split-K = 2)
    k_gemm_px<<<dim3(N_ROWS / 64, 2), 256>>>(P, x, p_Px);

    // M_irr = x@Wi0 + (Ld@x)@Wi1 ;  M_sol = x@Ws0 + (Lu@x)@Ws1
    k_gemm2<false><<<N_ROWS / 32, 256>>>(x, p_Ldx, Wi_w, Wi_w + 128 * 128, p_Mirr);
    k_gemm2<false><<<N_ROWS / 32, 256>>>(x, p_Lux, Ws_w, Ws_w + 128 * 128, p_Msol);
    // z = (Px0 + Px1)@Wh + total_bias   (same W applied to both split-K slabs)
    k_gemm2<true><<<N_ROWS / 32, 256>>>(p_Px, p_Px + N_ROWS * 128, Wh_w, Wh_w, z);

    // z += softmax(Ld-masked) @ M_irr ;  z += softmax(Lu-masked) @ M_sol
    k_attn<<<N_ROWS, 128>>>(Ld, p_Mirr, p_s + 0 * N_ROWS, p_s + 1 * N_ROWS, p_rowmax, z);
    k_attn<<<N_ROWS, 128>>>(Lu, p_Msol, p_s + 2 * N_ROWS, p_s + 3 * N_ROWS, p_rowmax + N_ROWS, z);
}

// round 5
// speedup vs baseline: 1.3335x; 1.3213x over previous
#include <cuda_runtime.h>
#include <cstdint>

#define NR 4096
#define NRL ((size_t)4096)

// ---------------- device scratch ----------------
__device__ float g_v[4][128];
__device__ float g_c[4];
__device__ float g_bias[128];
__device__ float g_s[4][NR];            // s1_irr, s2_irr, s1_sol, s2_sol
__device__ float g_M2[2];               // max_j s2
__device__ float g_fA[2][NR], g_fB[2][NR], g_fC[2][NR], g_fD[2][NR];
__device__ float g_xT[128 * NR];        // x^T, tf32-rna
__device__ float g_MT[2][128 * NR];     // M_irr^T, M_sol^T, tf32-rna
__device__ float g_Ldx[NR * 128];
__device__ float g_Lux[NR * 128];
__device__ float g_Px[NR * 128];
__device__ float g_Mirr[NR * 128];
__device__ float g_Msol[NR * 128];
__device__ float g_num[2][NR * 128];
__device__ float g_den[2][NR];

// ---------------- helpers ----------------
__device__ __forceinline__ uint32_t cvt_tf32(float v) {
    uint32_t r;
    asm("cvt.rna.tf32.f32 %0, %1;" : "=r"(r) : "f"(v));
    return r;
}
__device__ __forceinline__ float cvtf(float v) { return __uint_as_float(cvt_tf32(v)); }
__device__ __forceinline__ uint32_t smem_u32(const void* p) {
    uint32_t a;
    asm("{ .reg .u64 t; cvta.to.shared.u64 t, %1; cvt.u32.u64 %0, t; }" : "=r"(a) : "l"(p));
    return a;
}
__device__ __forceinline__ void cpasync16(uint32_t dst, const void* src) {
    asm volatile("cp.async.cg.shared.global [%0], [%1], 16;" :: "r"(dst), "l"(src) : "memory");
}
#define CP_COMMIT() asm volatile("cp.async.commit_group;" ::: "memory")
#define CP_WAIT0()  asm volatile("cp.async.wait_group 0;" ::: "memory")

#define MMA_TF32(c, a, b0, b1) \
    asm volatile("mma.sync.aligned.m16n8k8.row.col.f32.tf32.tf32.f32 " \
        "{%0,%1,%2,%3}, {%4,%5,%6,%7}, {%8,%9}, {%0,%1,%2,%3};" \
        : "+f"((c)[0]), "+f"((c)[1]), "+f"((c)[2]), "+f"((c)[3]) \
        : "r"((a)[0]), "r"((a)[1]), "r"((a)[2]), "r"((a)[3]), "r"(b0), "r"(b1))

#define TSTR 36            // smem row stride (floats): bank = (4*gid+tig)&31, conflict-free
#define TILEF (128 * TSTR) // 4608 floats per tile

// ---------------- small prep kernels ----------------
__global__ void k_prep(const float* __restrict__ Wi_w, const float* __restrict__ Wi_b,
                       const float* __restrict__ Ws_w, const float* __restrict__ Ws_b,
                       const float* __restrict__ Wh_b,
                       const float* __restrict__ att_irr, const float* __restrict__ att_sol) {
    int c = threadIdx.x;
    float v1i = 0.f, v2i = 0.f, v1s = 0.f, v2s = 0.f;
    for (int j = 0; j < 2; j++)
        for (int o = 0; o < 128; o++) {
            int a = j * 128 + o;
            float wi = Wi_w[(j * 128 + c) * 128 + o];
            float ws = Ws_w[(j * 128 + c) * 128 + o];
            v1i += wi * att_irr[a];  v2i += wi * att_irr[256 + a];
            v1s += ws * att_sol[a];  v2s += ws * att_sol[256 + a];
        }
    g_v[0][c] = v1i; g_v[1][c] = v2i; g_v[2][c] = v1s; g_v[3][c] = v2s;
    float c1i = 0.f, c2i = 0.f, c1s = 0.f, c2s = 0.f;
    for (int j = 0; j < 2; j++) {
        int a = j * 128 + c;
        c1i += Wi_b[a] * att_irr[a];  c2i += Wi_b[a] * att_irr[256 + a];
        c1s += Ws_b[a] * att_sol[a];  c2s += Ws_b[a] * att_sol[256 + a];
    }
    __shared__ float red[4][128];
    red[0][c] = c1i; red[1][c] = c2i; red[2][c] = c1s; red[3][c] = c2s;
    __syncthreads();
    for (int s = 64; s > 0; s >>= 1) {
        if (c < s) for (int q = 0; q < 4; q++) red[q][c] += red[q][c + s];
        __syncthreads();
    }
    if (c < 4) g_c[c] = red[c][0];
    g_bias[c] = Wi_b[c] + Wi_b[128 + c] + Ws_b[c] + Ws_b[128 + c] + Wh_b[c];
}

__global__ void k_scores(const float* __restrict__ x) {
    int i = blockIdx.x, t = threadIdx.x;
    float xv = x[(size_t)i * 128 + t];
    __shared__ float red[4][128];
    red[0][t] = xv * g_v[0][t];
    red[1][t] = xv * g_v[1][t];
    red[2][t] = xv * g_v[2][t];
    red[3][t] = xv * g_v[3][t];
    __syncthreads();
    for (int s = 64; s > 0; s >>= 1) {
        if (t < s) for (int q = 0; q < 4; q++) red[q][t] += red[q][t + s];
        __syncthreads();
    }
    if (t < 4) g_s[t][i] = red[t][0] + g_c[t];
}

__global__ void k_m2() {
    int t = threadIdx.x;
    float m0 = -INFINITY, m1 = -INFINITY;
    for (int i = t; i < NR; i += 256) {
        m0 = fmaxf(m0, g_s[1][i]);
        m1 = fmaxf(m1, g_s[3][i]);
    }
    __shared__ float r0[256], r1[256];
    r0[t] = m0; r1[t] = m1;
    __syncthreads();
    for (int s = 128; s > 0; s >>= 1) {
        if (t < s) { r0[t] = fmaxf(r0[t], r0[t + s]); r1[t] = fmaxf(r1[t], r1[t + s]); }
        __syncthreads();
    }
    if (t == 0) { g_M2[0] = r0[0]; g_M2[1] = r1[0]; }
}

__global__ void k_factors() {
    int i = blockIdx.x * 256 + threadIdx.x;
    if (i >= NR) return;
    for (int mz = 0; mz < 2; mz++) {
        float s1 = g_s[2 * mz][i], s2 = g_s[2 * mz + 1][i];
        float a = s1 + g_M2[mz];
        float m = (a >= 0.f) ? a : 0.2f * a;
        g_fA[mz][i] = expf(s1 - m);
        g_fC[mz][i] = expf(0.2f * s1 - m);
        g_fB[mz][i] = expf(s2);
        g_fD[mz][i] = expf(0.2f * s2);
    }
}

// transpose [4096,128] -> [128,4096] with tf32-rna rounding
__global__ void k_T(const float* __restrict__ src, float* __restrict__ dst) {
    __shared__ float tl[32][129];
    int rb = blockIdx.x * 32, t = threadIdx.x;
    for (int i = t; i < 32 * 128; i += 256) {
        int r = i >> 7, c = i & 127;
        tl[r][c] = src[(size_t)(rb + r) * 128 + c];
    }
    __syncthreads();
    for (int i = t; i < 32 * 128; i += 256) {
        int c = i >> 5, r = i & 31;
        dst[(size_t)c * NRL + rb + r] = cvtf(tl[r][c]);
    }
}

// ---------------- tf32 mma.sync GEMM: out += A[128 rows][K] @ x[K][128] ----------------
#define SM_MMA (4 * TILEF * 4)          // 73728 bytes
__global__ __launch_bounds__(256) void k_mma_big(const float* __restrict__ Ld,
                                                 const float* __restrict__ Lu,
                                                 const float* __restrict__ P) {
    extern __shared__ float sm[];
    float* Asm[2] = {sm, sm + 2 * TILEF};
    float* Bsm[2] = {sm + TILEF, sm + 3 * TILEF};
    uint32_t smb = smem_u32(sm);
    uint32_t Bsb[2] = {smb + TILEF * 4, smb + 3 * TILEF * 4};

    int tid = threadIdx.x;
    int wid = tid >> 5, lane = tid & 31, gid = lane >> 2, tig = lane & 3;
    int wm = wid >> 1, wn = wid & 1;
    int row = tid >> 1, cb = (tid & 1) * 16;

    const float* A = (blockIdx.z == 0) ? Ld : ((blockIdx.z == 1) ? Lu : P);
    float* out = (blockIdx.z == 0) ? g_Ldx : ((blockIdx.z == 1) ? g_Lux : g_Px);
    int r0 = blockIdx.x * 128, kb = blockIdx.y * 2048;
    const int NC = 2048 / 32;

    size_t arow = (size_t)(r0 + row) * NRL + kb + cb;
    size_t brow = (size_t)row * NRL + kb + cb;

    float acc[2][8][4];
#pragma unroll
    for (int mi = 0; mi < 2; mi++)
#pragma unroll
        for (int ni = 0; ni < 8; ni++)
#pragma unroll
            for (int q = 0; q < 4; q++) acc[mi][ni][q] = 0.f;

    float4 ar[4];
    auto ldA = [&](int c) {
#pragma unroll
        for (int j = 0; j < 4; j++) ar[j] = *(const float4*)&A[arow + c * 32 + 4 * j];
    };
    auto stA = [&](int s) {
#pragma unroll
        for (int j = 0; j < 4; j++) {
            float4 v;
            v.x = cvtf(ar[j].x); v.y = cvtf(ar[j].y); v.z = cvtf(ar[j].z); v.w = cvtf(ar[j].w);
            *(float4*)&Asm[s][row * TSTR + cb + 4 * j] = v;
        }
    };
    auto cpB = [&](int s, int c) {
#pragma unroll
        for (int j = 0; j < 4; j++)
            cpasync16(Bsb[s] + (row * TSTR + cb + 4 * j) * 4, &g_xT[brow + c * 32 + 4 * j]);
        CP_COMMIT();
    };
    auto compute = [&](int s) {
        float* As_ = Asm[s];
        float* Bs_ = Bsm[s];
#pragma unroll
        for (int k8 = 0; k8 < 4; k8++) {
            int kk = k8 * 8;
            uint32_t a[2][4];
#pragma unroll
            for (int mi = 0; mi < 2; mi++) {
                int ar0 = wm * 32 + mi * 16 + gid;
                a[mi][0] = __float_as_uint(As_[ar0 * TSTR + kk + tig]);
                a[mi][1] = __float_as_uint(As_[(ar0 + 8) * TSTR + kk + tig]);
                a[mi][2] = __float_as_uint(As_[ar0 * TSTR + kk + tig + 4]);
                a[mi][3] = __float_as_uint(As_[(ar0 + 8) * TSTR + kk + tig + 4]);
            }
#pragma unroll
            for (int ni = 0; ni < 8; ni++) {
                int bc = wn * 64 + ni * 8 + gid;
                uint32_t b0 = __float_as_uint(Bs_[bc * TSTR + kk + tig]);
                uint32_t b1 = __float_as_uint(Bs_[bc * TSTR + kk + tig + 4]);
                MMA_TF32(acc[0][ni], a[0], b0, b1);
                MMA_TF32(acc[1][ni], a[1], b0, b1);
            }
        }
    };

    cpB(0, 0);
    ldA(0);
    for (int c = 0; c < NC; c++) {
        int s = c & 1;
        CP_WAIT0();
        __syncthreads();                       // everyone done with previous compute
        if (c + 1 < NC) cpB(s ^ 1, c + 1);     // overlap next B with this chunk's work
        stA(s);
        if (c + 1 < NC) ldA(c + 1);
        __syncthreads();
        compute(s);
    }
#pragma unroll
    for (int mi = 0; mi < 2; mi++)
#pragma unroll
        for (int ni = 0; ni < 8; ni++) {
            int orow = r0 + wm * 32 + mi * 16 + gid;
            int ocol = wn * 64 + ni * 8 + 2 * tig;
            atomicAdd(&out[(size_t)orow * 128 + ocol], acc[mi][ni][0]);
            atomicAdd(&out[(size_t)orow * 128 + ocol + 1], acc[mi][ni][1]);
            atomicAdd(&out[(size_t)(orow + 8) * 128 + ocol], acc[mi][ni][2]);
            atomicAdd(&out[(size_t)(orow + 8) * 128 + ocol + 1], acc[mi][ni][3]);
        }
}

// ---------------- fused masked-softmax attention (num/den) ----------------
#define SM_ATTN (4 * TILEF * 4 + 3 * 2048 * 4)   // 98304 bytes
__global__ __launch_bounds__(256) void k_attn(const float* __restrict__ Ld,
                                              const float* __restrict__ Lu) {
    extern __shared__ float sm[];
    float* Asm[2] = {sm, sm + 2 * TILEF};
    float* Bsm[2] = {sm + TILEF, sm + 3 * TILEF};
    float* s2c = sm + 4 * TILEF;
    float* Bc  = s2c + 2048;
    float* Dc  = Bc + 2048;
    uint32_t smb = smem_u32(sm);
    uint32_t Bsb[2] = {smb + TILEF * 4, smb + 3 * TILEF * 4};

    int tid = threadIdx.x;
    int wid = tid >> 5, lane = tid & 31, gid = lane >> 2, tig = lane & 3;
    int wm = wid >> 1, wn = wid & 1;
    int row = tid >> 1, cb = (tid & 1) * 16;

    int mz = blockIdx.z;
    const float* L = mz ? Lu : Ld;
    float* out = g_num[mz];
    int i0 = blockIdx.x * 128, kb = blockIdx.y * 2048;
    const int NC = 2048 / 32;

    // stage column factors once
    for (int i = tid; i < 2048; i += 256) {
        s2c[i] = g_s[2 * mz + 1][kb + i];
        Bc[i]  = g_fB[mz][kb + i];
        Dc[i]  = g_fD[mz][kb + i];
    }
    float s1 = g_s[2 * mz][i0 + row];
    float Ai = g_fA[mz][i0 + row];
    float Ci = g_fC[mz][i0 + row];
    float den_t = 0.f;
    __syncthreads();

    size_t lrow = (size_t)(i0 + row) * NRL + kb + cb;
    size_t brow = (size_t)row * NRL + kb + cb;

    float acc[2][8][4];
#pragma unroll
    for (int mi = 0; mi < 2; mi++)
#pragma unroll
        for (int ni = 0; ni < 8; ni++)
#pragma unroll
            for (int q = 0; q < 4; q++) acc[mi][ni][q] = 0.f;

    float4 Lr[4];
    auto ldL = [&](int c) {
#pragma unroll
        for (int j = 0; j < 4; j++) Lr[j] = *(const float4*)&L[lrow + c * 32 + 4 * j];
    };
    auto stW = [&](int s, int c) {
        int base = c * 32 + cb;
#pragma unroll
        for (int j = 0; j < 4; j++) {
            float4 lv = Lr[j];
            float4 s2v = *(float4*)&s2c[base + 4 * j];
            float4 Bv  = *(float4*)&Bc[base + 4 * j];
            float4 Dv  = *(float4*)&Dc[base + 4 * j];
            float w0 = (lv.x != 0.f) ? ((s1 + s2v.x >= 0.f) ? Ai * Bv.x : Ci * Dv.x) : 0.f;
            float w1 = (lv.y != 0.f) ? ((s1 + s2v.y >= 0.f) ? Ai * Bv.y : Ci * Dv.y) : 0.f;
            float w2 = (lv.z != 0.f) ? ((s1 + s2v.z >= 0.f) ? Ai * Bv.z : Ci * Dv.z) : 0.f;
            float w3 = (lv.w != 0.f) ? ((s1 + s2v.w >= 0.f) ? Ai * Bv.w : Ci * Dv.w) : 0.f;
            float4 v;
            v.x = cvtf(w0); v.y = cvtf(w1); v.z = cvtf(w2); v.w = cvtf(w3);
            den_t += v.x + v.y + v.z + v.w;
            *(float4*)&Asm[s][row * TSTR + cb + 4 * j] = v;
        }
    };
    auto cpB = [&](int s, int c) {
#pragma unroll
        for (int j = 0; j < 4; j++)
            cpasync16(Bsb[s] + (row * TSTR + cb + 4 * j) * 4, &g_MT[mz][brow + c * 32 + 4 * j]);
        CP_COMMIT();
    };
    auto compute = [&](int s) {
        float* As_ = Asm[s];
        float* Bs_ = Bsm[s];
#pragma unroll
        for (int k8 = 0; k8 < 4; k8++) {
            int kk = k8 * 8;
            uint32_t a[2][4];
#pragma unroll
            for (int mi = 0; mi < 2; mi++) {
                int ar0 = wm * 32 + mi * 16 + gid;
                a[mi][0] = __float_as_uint(As_[ar0 * TSTR + kk + tig]);
                a[mi][1] = __float_as_uint(As_[(ar0 + 8) * TSTR + kk + tig]);
                a[mi][2] = __float_as_uint(As_[ar0 * TSTR + kk + tig + 4]);
                a[mi][3] = __float_as_uint(As_[(ar0 + 8) * TSTR + kk + tig + 4]);
            }
#pragma unroll
            for (int ni = 0; ni < 8; ni++) {
                int bc = wn * 64 + ni * 8 + gid;
                uint32_t b0 = __float_as_uint(Bs_[bc * TSTR + kk + tig]);
                uint32_t b1 = __float_as_uint(Bs_[bc * TSTR + kk + tig + 4]);
                MMA_TF32(acc[0][ni], a[0], b0, b1);
                MMA_TF32(acc[1][ni], a[1], b0, b1);
            }
        }
    };

    cpB(0, 0);
    ldL(0);
    for (int c = 0; c < NC; c++) {
        int s = c & 1;
        CP_WAIT0();
        __syncthreads();
        if (c + 1 < NC) cpB(s ^ 1, c + 1);
        stW(s, c);
        if (c + 1 < NC) ldL(c + 1);
        __syncthreads();
        compute(s);
    }
#pragma unroll
    for (int mi = 0; mi < 2; mi++)
#pragma unroll
        for (int ni = 0; ni < 8; ni++) {
            int orow = i0 + wm * 32 + mi * 16 + gid;
            int ocol = wn * 64 + ni * 8 + 2 * tig;
            atomicAdd(&out[(size_t)orow * 128 + ocol], acc[mi][ni][0]);
            atomicAdd(&out[(size_t)orow * 128 + ocol + 1], acc[mi][ni][1]);
            atomicAdd(&out[(size_t)(orow + 8) * 128 + ocol], acc[mi][ni][2]);
            atomicAdd(&out[(size_t)(orow + 8) * 128 + ocol + 1], acc[mi][ni][3]);
        }
    atomicAdd(&g_den[mz][i0 + row], den_t);
}

// ---------------- epilogue SIMT GEMMs (K=128) ----------------
template <bool TWO, bool ADD_BIAS>
__global__ __launch_bounds__(256) void k_gemm2(const float* __restrict__ A1, const float* __restrict__ A2,
                                               const float* __restrict__ W1, const float* __restrict__ W2,
                                               float* __restrict__ C) {
    __shared__ float A1s[32][33];
    __shared__ float A2s[32][33];
    __shared__ float W1s[32][128];
    __shared__ float W2s[32][128];
    int tid = threadIdx.x;
    int bm = blockIdx.x * 32;
    int trow = (tid >> 5) * 4;
    int tcol = (tid & 31) * 4;
    int am = tid >> 3;
    int ak = (tid & 7) * 4;
    int wr = tid >> 5;
    int wc = (tid & 31) * 4;
    float acc[4][4];
#pragma unroll
    for (int r = 0; r < 4; r++)
#pragma unroll
        for (int c = 0; c < 4; c++) acc[r][c] = 0.f;

    for (int kk = 0; kk < 128; kk += 32) {
        float4 a1 = *(const float4*)&A1[(size_t)(bm + am) * 128 + kk + ak];
        A1s[ak + 0][am] = a1.x; A1s[ak + 1][am] = a1.y; A1s[ak + 2][am] = a1.z; A1s[ak + 3][am] = a1.w;
        if (TWO) {
            float4 a2 = *(const float4*)&A2[(size_t)(bm + am) * 128 + kk + ak];
            A2s[ak + 0][am] = a2.x; A2s[ak + 1][am] = a2.y; A2s[ak + 2][am] = a2.z; A2s[ak + 3][am] = a2.w;
        }
#pragma unroll
        for (int q = 0; q < 4; q++) {
            *(float4*)&W1s[wr + q * 8][wc] = *(const float4*)&W1[(size_t)(kk + wr + q * 8) * 128 + wc];
            if (TWO)
                *(float4*)&W2s[wr + q * 8][wc] = *(const float4*)&W2[(size_t)(kk + wr + q * 8) * 128 + wc];
        }
        __syncthreads();
#pragma unroll
        for (int k = 0; k < 32; k++) {
            float a1f[4], a2f[4];
#pragma unroll
            for (int r = 0; r < 4; r++) {
                a1f[r] = A1s[k][trow + r];
                if (TWO) a2f[r] = A2s[k][trow + r];
            }
            float4 w1v = *(float4*)&W1s[k][tcol];
            float4 w2v;
            if (TWO) w2v = *(float4*)&W2s[k][tcol];
#pragma unroll
            for (int r = 0; r < 4; r++) {
                acc[r][0] += a1f[r] * w1v.x;
                acc[r][1] += a1f[r] * w1v.y;
                acc[r][2] += a1f[r] * w1v.z;
                acc[r][3] += a1f[r] * w1v.w;
                if (TWO) {
                    acc[r][0] += a2f[r] * w2v.x;
                    acc[r][1] += a2f[r] * w2v.y;
                    acc[r][2] += a2f[r] * w2v.z;
                    acc[r][3] += a2f[r] * w2v.w;
                }
            }
        }
        __syncthreads();
    }
#pragma unroll
    for (int r = 0; r < 4; r++) {
        float4 o = make_float4(acc[r][0], acc[r][1], acc[r][2], acc[r][3]);
        if (ADD_BIAS) {
            o.x += g_bias[tcol + 0];
            o.y += g_bias[tcol + 1];
            o.z += g_bias[tcol + 2];
            o.w += g_bias[tcol + 3];
        }
        *(float4*)&C[(size_t)(bm + trow + r) * 128 + tcol] = o;
    }
}

__global__ void k_final(float* __restrict__ z) {
    int idx = blockIdx.x * 256 + threadIdx.x;
    int i = idx >> 7;
    float d0 = g_den[0][i]; if (!(d0 > 0.f)) d0 = 1.f;
    float d1 = g_den[1][i]; if (!(d1 > 0.f)) d1 = 1.f;
    z[idx] += g_num[0][idx] / d0 + g_num[1][idx] / d1;
}

// ---------------- host launcher ----------------
extern "C" void kernel_launch(void* const* d_in, const int* in_sizes, int n_in,
                              void* d_out, int out_size) {
    const float* x       = (const float*)d_in[0];
    const float* Lu      = (const float*)d_in[1];
    const float* Ld      = (const float*)d_in[2];
    const float* P       = (const float*)d_in[3];
    const float* Wi_w    = (const float*)d_in[4];
    const float* Wi_b    = (const float*)d_in[5];
    const float* Ws_w    = (const float*)d_in[6];
    const float* Ws_b    = (const float*)d_in[7];
    const float* Wh_w    = (const float*)d_in[8];
    const float* Wh_b    = (const float*)d_in[9];
    const float* att_irr = (const float*)d_in[10];
    const float* att_sol = (const float*)d_in[11];
    float* z = (float*)d_out;

    cudaFuncSetAttribute((const void*)k_mma_big, cudaFuncAttributeMaxDynamicSharedMemorySize, SM_MMA);
    cudaFuncSetAttribute((const void*)k_attn, cudaFuncAttributeMaxDynamicSharedMemorySize, SM_ATTN);

    float *p_Ldx, *p_Lux, *p_Px, *p_num, *p_den, *p_xT, *p_MT, *p_Mirr, *p_Msol;
    cudaGetSymbolAddress((void**)&p_Ldx, g_Ldx);
    cudaGetSymbolAddress((void**)&p_Lux, g_Lux);
    cudaGetSymbolAddress((void**)&p_Px, g_Px);
    cudaGetSymbolAddress((void**)&p_num, g_num);
    cudaGetSymbolAddress((void**)&p_den, g_den);
    cudaGetSymbolAddress((void**)&p_xT, g_xT);
    cudaGetSymbolAddress((void**)&p_MT, g_MT);
    cudaGetSymbolAddress((void**)&p_Mirr, g_Mirr);
    cudaGetSymbolAddress((void**)&p_Msol, g_Msol);

    cudaMemsetAsync(p_Ldx, 0, NR * 128 * sizeof(float));
    cudaMemsetAsync(p_Lux, 0, NR * 128 * sizeof(float));
    cudaMemsetAsync(p_Px, 0, NR * 128 * sizeof(float));
    cudaMemsetAsync(p_num, 0, 2 * NR * 128 * sizeof(float));
    cudaMemsetAsync(p_den, 0, 2 * NR * sizeof(float));

    k_prep<<<1, 128>>>(Wi_w, Wi_b, Ws_w, Ws_b, Wh_b, att_irr, att_sol);
    k_scores<<<NR, 128>>>(x);
    k_m2<<<1, 256>>>();
    k_factors<<<NR / 256, 256>>>();
    k_T<<<NR / 32, 256>>>(x, p_xT);

    k_mma_big<<<dim3(NR / 128, 2, 3), 256, SM_MMA>>>(Ld, Lu, P);

    k_gemm2<true, false><<<NR / 32, 256>>>(x, p_Ldx, Wi_w, Wi_w + 128 * 128, p_Mirr);
    k_gemm2<true, false><<<NR / 32, 256>>>(x, p_Lux, Ws_w, Ws_w + 128 * 128, p_Msol);
    k_gemm2<false, true><<<NR / 32, 256>>>(p_Px, nullptr, Wh_w, nullptr, z);

    k_T<<<NR / 32, 256>>>(p_Mirr, p_MT);
    k_T<<<NR / 32, 256>>>(p_Msol, p_MT + 128 * NR);

    k_attn<<<dim3(NR / 128, 2, 2), 256, SM_ATTN>>>(Ld, Lu);
    k_final<<<NR * 128 / 256, 256>>>(z);
}

// round 7
// speedup vs baseline: 2.0417x; 1.5311x over previous
#include <cuda_runtime.h>
#include <cuda_fp16.h>
#include <cstdint>
#include <cstring>

#define NR 4096
#define NRL ((size_t)4096)

// ---------------- device scratch ----------------
__device__ float g_v[4][128];
__device__ float g_c[4];
__device__ float g_bias[128];
__device__ float g_s[4][NR];            // s1_irr, s2_irr, s1_sol, s2_sol
__device__ float g_M2[2];
__device__ float g_fA[2][NR], g_fB[2][NR], g_fC[2][NR], g_fD[2][NR];
__device__ __half g_xTh[128 * NR];      // x^T (half)
__device__ __half g_MTh[2][128 * NR];   // M_irr^T, M_sol^T (half)
__device__ float g_Ldx[NR * 128];
__device__ float g_Lux[NR * 128];
__device__ float g_Px[NR * 128];
__device__ float g_num[2][NR * 128];
__device__ float g_den[2][NR];

// ---------------- helpers ----------------
__device__ __forceinline__ uint32_t h2u(__half2 h) {
    uint32_t u;
    memcpy(&u, &h, 4);
    return u;
}
__device__ __forceinline__ uint32_t smem_u32(const void* p) {
    uint32_t a;
    asm("{ .reg .u64 t; cvta.to.shared.u64 t, %1; cvt.u32.u64 %0, t; }" : "=r"(a) : "l"(p));
    return a;
}
__device__ __forceinline__ void cpasync16(uint32_t dst, const void* src) {
    asm volatile("cp.async.cg.shared.global [%0], [%1], 16;" :: "r"(dst), "l"(src) : "memory");
}
#define CP_COMMIT() asm volatile("cp.async.commit_group;" ::: "memory")
#define CP_WAIT0()  asm volatile("cp.async.wait_group 0;" ::: "memory")

#define MMA_F16(c, a, b0, b1) \
    asm volatile("mma.sync.aligned.m16n8k16.row.col.f32.f16.f16.f32 " \
        "{%0,%1,%2,%3}, {%4,%5,%6,%7}, {%8,%9}, {%0,%1,%2,%3};" \
        : "+f"((c)[0]), "+f"((c)[1]), "+f"((c)[2]), "+f"((c)[3]) \
        : "r"((a)[0]), "r"((a)[1]), "r"((a)[2]), "r"((a)[3]), "r"(b0), "r"(b1))

// smem tile: 128 rows x 32 halves (chunk), row stride = 20 words (40 halves).
// bank(gid,tig) = (20*gid + tig) & 31 is a perfect 32-permutation -> conflict-free frags.
#define WPR 20                 // words per row
#define TILEW (128 * WPR)      // 2560 words per tile
#define KSPLIT 4
#define KSLAB (NR / KSPLIT)    // 1024
#define NCHUNK (KSLAB / 32)    // 32

// ---------------- small prep kernels ----------------
__global__ void k_prep(const float* __restrict__ Wi_w, const float* __restrict__ Wi_b,
                       const float* __restrict__ Ws_w, const float* __restrict__ Ws_b,
                       const float* __restrict__ Wh_b,
                       const float* __restrict__ att_irr, const float* __restrict__ att_sol) {
    int c = threadIdx.x;
    float v1i = 0.f, v2i = 0.f, v1s = 0.f, v2s = 0.f;
    for (int j = 0; j < 2; j++)
        for (int o = 0; o < 128; o++) {
            int a = j * 128 + o;
            float wi = Wi_w[(j * 128 + c) * 128 + o];
            float ws = Ws_w[(j * 128 + c) * 128 + o];
            v1i += wi * att_irr[a];  v2i += wi * att_irr[256 + a];
            v1s += ws * att_sol[a];  v2s += ws * att_sol[256 + a];
        }
    g_v[0][c] = v1i; g_v[1][c] = v2i; g_v[2][c] = v1s; g_v[3][c] = v2s;
    float c1i = 0.f, c2i = 0.f, c1s = 0.f, c2s = 0.f;
    for (int j = 0; j < 2; j++) {
        int a = j * 128 + c;
        c1i += Wi_b[a] * att_irr[a];  c2i += Wi_b[a] * att_irr[256 + a];
        c1s += Ws_b[a] * att_sol[a];  c2s += Ws_b[a] * att_sol[256 + a];
    }
    __shared__ float red[4][128];
    red[0][c] = c1i; red[1][c] = c2i; red[2][c] = c1s; red[3][c] = c2s;
    __syncthreads();
    for (int s = 64; s > 0; s >>= 1) {
        if (c < s) for (int q = 0; q < 4; q++) red[q][c] += red[q][c + s];
        __syncthreads();
    }
    if (c < 4) g_c[c] = red[c][0];
    g_bias[c] = Wi_b[c] + Wi_b[128 + c] + Ws_b[c] + Ws_b[128 + c] + Wh_b[c];
}

__global__ void k_scores(const float* __restrict__ x) {
    int i = blockIdx.x, t = threadIdx.x;
    float xv = x[(size_t)i * 128 + t];
    __shared__ float red[4][128];
    red[0][t] = xv * g_v[0][t];
    red[1][t] = xv * g_v[1][t];
    red[2][t] = xv * g_v[2][t];
    red[3][t] = xv * g_v[3][t];
    __syncthreads();
    for (int s = 64; s > 0; s >>= 1) {
        if (t < s) for (int q = 0; q < 4; q++) red[q][t] += red[q][t + s];
        __syncthreads();
    }
    if (t < 4) g_s[t][i] = red[t][0] + g_c[t];
}

__global__ void k_m2() {
    int t = threadIdx.x;
    float m0 = -INFINITY, m1 = -INFINITY;
    for (int i = t; i < NR; i += 256) {
        m0 = fmaxf(m0, g_s[1][i]);
        m1 = fmaxf(m1, g_s[3][i]);
    }
    __shared__ float r0[256], r1[256];
    r0[t] = m0; r1[t] = m1;
    __syncthreads();
    for (int s = 128; s > 0; s >>= 1) {
        if (t < s) { r0[t] = fmaxf(r0[t], r0[t + s]); r1[t] = fmaxf(r1[t], r1[t + s]); }
        __syncthreads();
    }
    if (t == 0) { g_M2[0] = r0[0]; g_M2[1] = r1[0]; }
}

__global__ void k_factors() {
    int i = blockIdx.x * 256 + threadIdx.x;
    if (i >= NR) return;
    for (int mz = 0; mz < 2; mz++) {
        float s1 = g_s[2 * mz][i], s2 = g_s[2 * mz + 1][i];
        float a = s1 + g_M2[mz];
        float m = (a >= 0.f) ? a : 0.2f * a;
        g_fA[mz][i] = expf(s1 - m);
        g_fC[mz][i] = expf(0.2f * s1 - m);
        g_fB[mz][i] = expf(s2);
        g_fD[mz][i] = expf(0.2f * s2);
    }
}

// transpose x [4096,128] -> half [128,4096]
__global__ void k_Tx(const float* __restrict__ src, __half* __restrict__ dst) {
    __shared__ float tl[32][129];
    int rb = blockIdx.x * 32, t = threadIdx.x;
    for (int i = t; i < 32 * 128; i += 256) {
        int r = i >> 7, c = i & 127;
        tl[r][c] = src[(size_t)(rb + r) * 128 + c];
    }
    __syncthreads();
    for (int i = t; i < 32 * 128; i += 256) {
        int c = i >> 5, r = i & 31;
        dst[(size_t)c * NRL + rb + r] = __float2half_rn(tl[r][c]);
    }
}

// ---------------- fp16 mma GEMM: out += A[4096x4096] @ x[4096x128] ----------------
#define SM_MMA (4 * TILEW * 4)     // 40960 bytes
__global__ __launch_bounds__(256) void k_mma_big(const float* __restrict__ Ld,
                                                 const float* __restrict__ Lu,
                                                 const float* __restrict__ P) {
    extern __shared__ uint32_t smw[];
    uint32_t* Asw[2] = {smw, smw + 2 * TILEW};
    uint32_t* Bsw[2] = {smw + TILEW, smw + 3 * TILEW};
    uint32_t smb = smem_u32(smw);
    uint32_t Bsb[2] = {smb + TILEW * 4, smb + 3 * TILEW * 4};

    int tid = threadIdx.x;
    int wid = tid >> 5, lane = tid & 31, gid = lane >> 2, tig = lane & 3;
    int wm = wid >> 1, wn = wid & 1;
    int row = tid >> 1, hb = tid & 1;   // each (row, half) pair covers 16 fp32 cols

    const float* A = (blockIdx.z == 0) ? Ld : ((blockIdx.z == 1) ? Lu : P);
    float* out = (blockIdx.z == 0) ? g_Ldx : ((blockIdx.z == 1) ? g_Lux : g_Px);
    int r0 = blockIdx.x * 128, kb = blockIdx.y * KSLAB;

    size_t arow = (size_t)(r0 + row) * NRL + kb + hb * 16;
    const __half* bsrc = &g_xTh[(size_t)row * NRL + kb + hb * 16];

    float acc[2][8][4];
#pragma unroll
    for (int mi = 0; mi < 2; mi++)
#pragma unroll
        for (int ni = 0; ni < 8; ni++)
#pragma unroll
            for (int q = 0; q < 4; q++) acc[mi][ni][q] = 0.f;

    float4 ar[4];
    auto ldA = [&](int c) {
#pragma unroll
        for (int j = 0; j < 4; j++) ar[j] = *(const float4*)&A[arow + c * 32 + 4 * j];
    };
    auto stA = [&](int s) {
        uint32_t h[8];
#pragma unroll
        for (int j = 0; j < 4; j++) {
            h[2 * j]     = h2u(__floats2half2_rn(ar[j].x, ar[j].y));
            h[2 * j + 1] = h2u(__floats2half2_rn(ar[j].z, ar[j].w));
        }
        uint32_t* d = &Asw[s][row * WPR + hb * 8];
        *(uint4*)d = make_uint4(h[0], h[1], h[2], h[3]);
        *(uint4*)(d + 4) = make_uint4(h[4], h[5], h[6], h[7]);
    };
    auto cpB = [&](int s, int c) {
        uint32_t d = Bsb[s] + (row * WPR + hb * 8) * 4;
        cpasync16(d, bsrc + c * 32);
        cpasync16(d + 16, bsrc + c * 32 + 8);
        CP_COMMIT();
    };
    auto compute = [&](int s) {
        uint32_t* As_ = Asw[s];
        uint32_t* Bs_ = Bsw[s];
#pragma unroll
        for (int k16 = 0; k16 < 2; k16++) {
            int kw = k16 * 8 + tig;
            uint32_t a[2][4];
#pragma unroll
            for (int mi = 0; mi < 2; mi++) {
                int ar0 = wm * 32 + mi * 16 + gid;
                a[mi][0] = As_[ar0 * WPR + kw];
                a[mi][1] = As_[(ar0 + 8) * WPR + kw];
                a[mi][2] = As_[ar0 * WPR + kw + 4];
                a[mi][3] = As_[(ar0 + 8) * WPR + kw + 4];
            }
#pragma unroll
            for (int ni = 0; ni < 8; ni++) {
                int bc = wn * 64 + ni * 8 + gid;
                uint32_t b0 = Bs_[bc * WPR + kw];
                uint32_t b1 = Bs_[bc * WPR + kw + 4];
                MMA_F16(acc[0][ni], a[0], b0, b1);
                MMA_F16(acc[1][ni], a[1], b0, b1);
            }
        }
    };

    cpB(0, 0);
    ldA(0);
    for (int c = 0; c < NCHUNK; c++) {
        int s = c & 1;
        CP_WAIT0();
        __syncthreads();
        if (c + 1 < NCHUNK) cpB(s ^ 1, c + 1);
        stA(s);
        if (c + 1 < NCHUNK) ldA(c + 1);
        __syncthreads();
        compute(s);
    }
#pragma unroll
    for (int mi = 0; mi < 2; mi++)
#pragma unroll
        for (int ni = 0; ni < 8; ni++) {
            int orow = r0 + wm * 32 + mi * 16 + gid;
            int ocol = wn * 64 + ni * 8 + 2 * tig;
            atomicAdd(&out[(size_t)orow * 128 + ocol], acc[mi][ni][0]);
            atomicAdd(&out[(size_t)orow * 128 + ocol + 1], acc[mi][ni][1]);
            atomicAdd(&out[(size_t)(orow + 8) * 128 + ocol], acc[mi][ni][2]);
            atomicAdd(&out[(size_t)(orow + 8) * 128 + ocol + 1], acc[mi][ni][3]);
        }
}

// ---------------- fused masked-softmax attention (num/den) ----------------
#define SM_ATTN (4 * TILEW * 4 + 3 * KSLAB * 4)   // 40960 + 12288
__global__ __launch_bounds__(256) void k_attn(const float* __restrict__ Ld,
                                              const float* __restrict__ Lu) {
    extern __shared__ uint32_t smw[];
    uint32_t* Asw[2] = {smw, smw + 2 * TILEW};
    uint32_t* Bsw[2] = {smw + TILEW, smw + 3 * TILEW};
    float* s2c = (float*)(smw + 4 * TILEW);
    float* Bc  = s2c + KSLAB;
    float* Dc  = Bc + KSLAB;
    uint32_t smb = smem_u32(smw);
    uint32_t Bsb[2] = {smb + TILEW * 4, smb + 3 * TILEW * 4};

    int tid = threadIdx.x;
    int wid = tid >> 5, lane = tid & 31, gid = lane >> 2, tig = lane & 3;
    int wm = wid >> 1, wn = wid & 1;
    int row = tid >> 1, hb = tid & 1;

    int mz = blockIdx.z;
    const float* L = mz ? Lu : Ld;
    float* out = g_num[mz];
    int i0 = blockIdx.x * 128, kb = blockIdx.y * KSLAB;

    for (int i = tid; i < KSLAB; i += 256) {
        s2c[i] = g_s[2 * mz + 1][kb + i];
        Bc[i]  = g_fB[mz][kb + i];
        Dc[i]  = g_fD[mz][kb + i];
    }
    float s1 = g_s[2 * mz][i0 + row];
    float Ai = g_fA[mz][i0 + row];
    float Ci = g_fC[mz][i0 + row];
    float den_t = 0.f;
    __syncthreads();

    size_t lrow = (size_t)(i0 + row) * NRL + kb + hb * 16;
    const __half* bsrc = &g_MTh[mz][(size_t)row * NRL + kb + hb * 16];

    float acc[2][8][4];
#pragma unroll
    for (int mi = 0; mi < 2; mi++)
#pragma unroll
        for (int ni = 0; ni < 8; ni++)
#pragma unroll
            for (int q = 0; q < 4; q++) acc[mi][ni][q] = 0.f;

    float4 Lr[4];
    auto ldL = [&](int c) {
#pragma unroll
        for (int j = 0; j < 4; j++) Lr[j] = *(const float4*)&L[lrow + c * 32 + 4 * j];
    };
    auto stW = [&](int s, int c) {
        int base = c * 32 + hb * 16;
        uint32_t h[8];
#pragma unroll
        for (int j = 0; j < 4; j++) {
            float4 lv = Lr[j];
            float4 s2v = *(float4*)&s2c[base + 4 * j];
            float4 Bv  = *(float4*)&Bc[base + 4 * j];
            float4 Dv  = *(float4*)&Dc[base + 4 * j];
            float w0 = (lv.x != 0.f) ? ((s1 + s2v.x >= 0.f) ? Ai * Bv.x : Ci * Dv.x) : 0.f;
            float w1 = (lv.y != 0.f) ? ((s1 + s2v.y >= 0.f) ? Ai * Bv.y : Ci * Dv.y) : 0.f;
            float w2 = (lv.z != 0.f) ? ((s1 + s2v.z >= 0.f) ? Ai * Bv.z : Ci * Dv.z) : 0.f;
            float w3 = (lv.w != 0.f) ? ((s1 + s2v.w >= 0.f) ? Ai * Bv.w : Ci * Dv.w) : 0.f;
            __half2 p0 = __floats2half2_rn(w0, w1);
            __half2 p1 = __floats2half2_rn(w2, w3);
            den_t += __low2float(p0) + __high2float(p0) + __low2float(p1) + __high2float(p1);
            h[2 * j] = h2u(p0);
            h[2 * j + 1] = h2u(p1);
        }
        uint32_t* d = &Asw[s][row * WPR + hb * 8];
        *(uint4*)d = make_uint4(h[0], h[1], h[2], h[3]);
        *(uint4*)(d + 4) = make_uint4(h[4], h[5], h[6], h[7]);
    };
    auto cpB = [&](int s, int c) {
        uint32_t d = Bsb[s] + (row * WPR + hb * 8) * 4;
        cpasync16(d, bsrc + c * 32);
        cpasync16(d + 16, bsrc + c * 32 + 8);
        CP_COMMIT();
    };
    auto compute = [&](int s) {
        uint32_t* As_ = Asw[s];
        uint32_t* Bs_ = Bsw[s];
#pragma unroll
        for (int k16 = 0; k16 < 2; k16++) {
            int kw = k16 * 8 + tig;
            uint32_t a[2][4];
#pragma unroll
            for (int mi = 0; mi < 2; mi++) {
                int ar0 = wm * 32 + mi * 16 + gid;
                a[mi][0] = As_[ar0 * WPR + kw];
                a[mi][1] = As_[(ar0 + 8) * WPR + kw];
                a[mi][2] = As_[ar0 * WPR + kw + 4];
                a[mi][3] = As_[(ar0 + 8) * WPR + kw + 4];
            }
#pragma unroll
            for (int ni = 0; ni < 8; ni++) {
                int bc = wn * 64 + ni * 8 + gid;
                uint32_t b0 = Bs_[bc * WPR + kw];
                uint32_t b1 = Bs_[bc * WPR + kw + 4];
                MMA_F16(acc[0][ni], a[0], b0, b1);
                MMA_F16(acc[1][ni], a[1], b0, b1);
            }
        }
    };

    cpB(0, 0);
    ldL(0);
    for (int c = 0; c < NCHUNK; c++) {
        int s = c & 1;
        CP_WAIT0();
        __syncthreads();
        if (c + 1 < NCHUNK) cpB(s ^ 1, c + 1);
        stW(s, c);
        if (c + 1 < NCHUNK) ldL(c + 1);
        __syncthreads();
        compute(s);
    }
#pragma unroll
    for (int mi = 0; mi < 2; mi++)
#pragma unroll
        for (int ni = 0; ni < 8; ni++) {
            int orow = i0 + wm * 32 + mi * 16 + gid;
            int ocol = wn * 64 + ni * 8 + 2 * tig;
            atomicAdd(&out[(size_t)orow * 128 + ocol], acc[mi][ni][0]);
            atomicAdd(&out[(size_t)orow * 128 + ocol + 1], acc[mi][ni][1]);
            atomicAdd(&out[(size_t)(orow + 8) * 128 + ocol], acc[mi][ni][2]);
            atomicAdd(&out[(size_t)(orow + 8) * 128 + ocol + 1], acc[mi][ni][3]);
        }
    atomicAdd(&g_den[mz][i0 + row], den_t);
}

// ---------------- epilogue GEMMs (K=128) ----------------
// TRANS_HALF: write transposed half output MT[col][row]; else fp32 C[row][col] (+bias)
template <bool TWO, bool TRANS_HALF, bool ADD_BIAS>
__global__ __launch_bounds__(256) void k_gemm2(const float* __restrict__ A1, const float* __restrict__ A2,
                                               const float* __restrict__ W1, const float* __restrict__ W2,
                                               float* __restrict__ C, __half* __restrict__ CT) {
    __shared__ float A1s[32][33];
    __shared__ float A2s[32][33];
    __shared__ float W1s[32][128];
    __shared__ float W2s[32][128];
    __shared__ __half stg[32][136];
    int tid = threadIdx.x;
    int bm = blockIdx.x * 32;
    int trow = (tid >> 5) * 4;
    int tcol = (tid & 31) * 4;
    int am = tid >> 3;
    int ak = (tid & 7) * 4;
    int wr = tid >> 5;
    int wc = (tid & 31) * 4;
    float acc[4][4];
#pragma unroll
    for (int r = 0; r < 4; r++)
#pragma unroll
        for (int c = 0; c < 4; c++) acc[r][c] = 0.f;

    for (int kk = 0; kk < 128; kk += 32) {
        float4 a1 = *(const float4*)&A1[(size_t)(bm + am) * 128 + kk + ak];
        A1s[ak + 0][am] = a1.x; A1s[ak + 1][am] = a1.y; A1s[ak + 2][am] = a1.z; A1s[ak + 3][am] = a1.w;
        if (TWO) {
            float4 a2 = *(const float4*)&A2[(size_t)(bm + am) * 128 + kk + ak];
            A2s[ak + 0][am] = a2.x; A2s[ak + 1][am] = a2.y; A2s[ak + 2][am] = a2.z; A2s[ak + 3][am] = a2.w;
        }
#pragma unroll
        for (int q = 0; q < 4; q++) {
            *(float4*)&W1s[wr + q * 8][wc] = *(const float4*)&W1[(size_t)(kk + wr + q * 8) * 128 + wc];
            if (TWO)
                *(float4*)&W2s[wr + q * 8][wc] = *(const float4*)&W2[(size_t)(kk + wr + q * 8) * 128 + wc];
        }
        __syncthreads();
#pragma unroll
        for (int k = 0; k < 32; k++) {
            float a1f[4], a2f[4];
#pragma unroll
            for (int r = 0; r < 4; r++) {
                a1f[r] = A1s[k][trow + r];
                if (TWO) a2f[r] = A2s[k][trow + r];
            }
            float4 w1v = *(float4*)&W1s[k][tcol];
            float4 w2v;
            if (TWO) w2v = *(float4*)&W2s[k][tcol];
#pragma unroll
            for (int r = 0; r < 4; r++) {
                acc[r][0] += a1f[r] * w1v.x;
                acc[r][1] += a1f[r] * w1v.y;
                acc[r][2] += a1f[r] * w1v.z;
                acc[r][3] += a1f[r] * w1v.w;
                if (TWO) {
                    acc[r][0] += a2f[r] * w2v.x;
                    acc[r][1] += a2f[r] * w2v.y;
                    acc[r][2] += a2f[r] * w2v.z;
                    acc[r][3] += a2f[r] * w2v.w;
                }
            }
        }
        __syncthreads();
    }
    if (TRANS_HALF) {
#pragma unroll
        for (int r = 0; r < 4; r++)
#pragma unroll
            for (int c = 0; c < 4; c++)
                stg[trow + r][tcol + c] = __float2half_rn(acc[r][c]);
        __syncthreads();
        int col = tid >> 1, r0 = (tid & 1) * 16;
        __half hv[16];
#pragma unroll
        for (int j = 0; j < 16; j++) hv[j] = stg[r0 + j][col];
        *(uint4*)&CT[(size_t)col * NRL + bm + r0] = *(uint4*)&hv[0];
        *(uint4*)&CT[(size_t)col * NRL + bm + r0 + 8] = *(uint4*)&hv[8];
    } else {
#pragma unroll
        for (int r = 0; r < 4; r++) {
            float4 o = make_float4(acc[r][0], acc[r][1], acc[r][2], acc[r][3]);
            if (ADD_BIAS) {
                o.x += g_bias[tcol + 0];
                o.y += g_bias[tcol + 1];
                o.z += g_bias[tcol + 2];
                o.w += g_bias[tcol + 3];
            }
            *(float4*)&C[(size_t)(bm + trow + r) * 128 + tcol] = o;
        }
    }
}

__global__ void k_final(float* __restrict__ z) {
    int idx = blockIdx.x * 256 + threadIdx.x;
    int i = idx >> 7;
    float d0 = g_den[0][i]; if (!(d0 > 0.f)) d0 = 1.f;
    float d1 = g_den[1][i]; if (!(d1 > 0.f)) d1 = 1.f;
    z[idx] += g_num[0][idx] / d0 + g_num[1][idx] / d1;
}

// ---------------- host launcher ----------------
extern "C" void kernel_launch(void* const* d_in, const int* in_sizes, int n_in,
                              void* d_out, int out_size) {
    const float* x       = (const float*)d_in[0];
    const float* Lu      = (const float*)d_in[1];
    const float* Ld      = (const float*)d_in[2];
    const float* P       = (const float*)d_in[3];
    const float* Wi_w    = (const float*)d_in[4];
    const float* Wi_b    = (const float*)d_in[5];
    const float* Ws_w    = (const float*)d_in[6];
    const float* Ws_b    = (const float*)d_in[7];
    const float* Wh_w    = (const float*)d_in[8];
    const float* Wh_b    = (const float*)d_in[9];
    const float* att_irr = (const float*)d_in[10];
    const float* att_sol = (const float*)d_in[11];
    float* z = (float*)d_out;

    cudaFuncSetAttribute((const void*)k_mma_big, cudaFuncAttributeMaxDynamicSharedMemorySize, SM_MMA);
    cudaFuncSetAttribute((const void*)k_attn, cudaFuncAttributeMaxDynamicSharedMemorySize, SM_ATTN);

    float *p_Ldx, *p_Lux, *p_Px, *p_num, *p_den;
    __half *p_xTh, *p_MTh;
    cudaGetSymbolAddress((void**)&p_Ldx, g_Ldx);
    cudaGetSymbolAddress((void**)&p_Lux, g_Lux);
    cudaGetSymbolAddress((void**)&p_Px, g_Px);
    cudaGetSymbolAddress((void**)&p_num, g_num);
    cudaGetSymbolAddress((void**)&p_den, g_den);
    cudaGetSymbolAddress((void**)&p_xTh, g_xTh);
    cudaGetSymbolAddress((void**)&p_MTh, g_MTh);

    cudaMemsetAsync(p_Ldx, 0, NR * 128 * sizeof(float));
    cudaMemsetAsync(p_Lux, 0, NR * 128 * sizeof(float));
    cudaMemsetAsync(p_Px, 0, NR * 128 * sizeof(float));
    cudaMemsetAsync(p_num, 0, 2 * NR * 128 * sizeof(float));
    cudaMemsetAsync(p_den, 0, 2 * NR * sizeof(float));

    k_prep<<<1, 128>>>(Wi_w, Wi_b, Ws_w, Ws_b, Wh_b, att_irr, att_sol);
    k_scores<<<NR, 128>>>(x);
    k_m2<<<1, 256>>>();
    k_factors<<<NR / 256, 256>>>();
    k_Tx<<<NR / 32, 256>>>(x, p_xTh);

    k_mma_big<<<dim3(NR / 128, KSPLIT, 3), 256, SM_MMA>>>(Ld, Lu, P);

    // MT_irr = (x@Wi0 + Ldx@Wi1)^T (half), MT_sol likewise; z = Px@Wh + bias
    k_gemm2<true, true, false><<<NR / 32, 256>>>(x, p_Ldx, Wi_w, Wi_w + 128 * 128, nullptr, p_MTh);
    k_gemm2<true, true, false><<<NR / 32, 256>>>(x, p_Lux, Ws_w, Ws_w + 128 * 128, nullptr, p_MTh + 128 * NRL);
    k_gemm2<false, false, true><<<NR / 32, 256>>>(p_Px, nullptr, Wh_w, nullptr, z, nullptr);

    k_attn<<<dim3(NR / 128, KSPLIT, 2), 256, SM_ATTN>>>(Ld, Lu);
    k_final<<<NR * 128 / 256, 256>>>(z);
}

// round 8
// speedup vs baseline: 2.2941x; 1.1236x over previous
#include <cuda_runtime.h>
#include <cuda_fp16.h>
#include <cstdint>
#include <cstring>

#define NR 4096
#define NRL ((size_t)4096)
#define SLAB ((size_t)(NR * 128))

// ---------------- device scratch ----------------
__device__ float g_v[4][128];
__device__ float g_c[4];
__device__ float g_bias[128];
__device__ float g_s[4][NR];            // s1_irr, s2_irr, s1_sol, s2_sol
__device__ float g_M2[2];
__device__ float g_fA[2][NR], g_fB[2][NR], g_fC[2][NR], g_fD[2][NR];
__device__ __half g_xTh[128 * NR];      // x^T (half)
__device__ __half g_MTh[2][128 * NR];   // M_irr^T, M_sol^T (half)
// per-K-split slab outputs (no atomics)
#define KSPLIT 8
__device__ float g_Lx[3][KSPLIT][NR * 128];   // Ldx, Lux, Px slabs
__device__ float g_num[2][KSPLIT][NR * 128];
__device__ float g_den[2][NR];

// ---------------- helpers ----------------
__device__ __forceinline__ uint32_t h2u(__half2 h) {
    uint32_t u;
    memcpy(&u, &h, 4);
    return u;
}
__device__ __forceinline__ uint32_t smem_u32(const void* p) {
    uint32_t a;
    asm("{ .reg .u64 t; cvta.to.shared.u64 t, %1; cvt.u32.u64 %0, t; }" : "=r"(a) : "l"(p));
    return a;
}
__device__ __forceinline__ void cpasync16(uint32_t dst, const void* src) {
    asm volatile("cp.async.cg.shared.global [%0], [%1], 16;" :: "r"(dst), "l"(src) : "memory");
}
#define CP_COMMIT() asm volatile("cp.async.commit_group;" ::: "memory")
#define CP_WAIT1()  asm volatile("cp.async.wait_group 1;" ::: "memory")
#define CP_WAIT0()  asm volatile("cp.async.wait_group 0;" ::: "memory")

#define MMA_F16(c, a, b0, b1) \
    asm volatile("mma.sync.aligned.m16n8k16.row.col.f32.f16.f16.f32 " \
        "{%0,%1,%2,%3}, {%4,%5,%6,%7}, {%8,%9}, {%0,%1,%2,%3};" \
        : "+f"((c)[0]), "+f"((c)[1]), "+f"((c)[2]), "+f"((c)[3]) \
        : "r"((a)[0]), "r"((a)[1]), "r"((a)[2]), "r"((a)[3]), "r"(b0), "r"(b1))

#define LDSM4(r, addr) \
    asm volatile("ldmatrix.sync.aligned.m8n8.x4.shared.b16 {%0,%1,%2,%3}, [%4];" \
        : "=r"((r)[0]), "=r"((r)[1]), "=r"((r)[2]), "=r"((r)[3]) : "r"(addr))

// smem tile: 128 rows x 32 halves, row stride = 20 words (conflict-free; rows r..r+7
// start at banks {0,20,8,28,16,4,24,12} -> perfect 32-bank cover for ldmatrix).
#define WPR 20
#define TILEW (128 * WPR)
#define KSLAB 512
#define NCHUNK (KSLAB / 32)    // 16

// ---------------- small prep kernels ----------------
__global__ void k_prep(const float* __restrict__ Wi_w, const float* __restrict__ Wi_b,
                       const float* __restrict__ Ws_w, const float* __restrict__ Ws_b,
                       const float* __restrict__ Wh_b,
                       const float* __restrict__ att_irr, const float* __restrict__ att_sol) {
    int c = threadIdx.x;
    float v1i = 0.f, v2i = 0.f, v1s = 0.f, v2s = 0.f;
    for (int j = 0; j < 2; j++)
        for (int o = 0; o < 128; o++) {
            int a = j * 128 + o;
            float wi = Wi_w[(j * 128 + c) * 128 + o];
            float ws = Ws_w[(j * 128 + c) * 128 + o];
            v1i += wi * att_irr[a];  v2i += wi * att_irr[256 + a];
            v1s += ws * att_sol[a];  v2s += ws * att_sol[256 + a];
        }
    g_v[0][c] = v1i; g_v[1][c] = v2i; g_v[2][c] = v1s; g_v[3][c] = v2s;
    float c1i = 0.f, c2i = 0.f, c1s = 0.f, c2s = 0.f;
    for (int j = 0; j < 2; j++) {
        int a = j * 128 + c;
        c1i += Wi_b[a] * att_irr[a];  c2i += Wi_b[a] * att_irr[256 + a];
        c1s += Ws_b[a] * att_sol[a];  c2s += Ws_b[a] * att_sol[256 + a];
    }
    __shared__ float red[4][128];
    red[0][c] = c1i; red[1][c] = c2i; red[2][c] = c1s; red[3][c] = c2s;
    __syncthreads();
    for (int s = 64; s > 0; s >>= 1) {
        if (c < s) for (int q = 0; q < 4; q++) red[q][c] += red[q][c + s];
        __syncthreads();
    }
    if (c < 4) g_c[c] = red[c][0];
    g_bias[c] = Wi_b[c] + Wi_b[128 + c] + Ws_b[c] + Ws_b[128 + c] + Wh_b[c];
}

// warp-per-row scores
__global__ void k_scores(const float* __restrict__ x) {
    int wid = threadIdx.x >> 5, lane = threadIdx.x & 31;
    int row = blockIdx.x * 8 + wid;
    float p0 = 0.f, p1 = 0.f, p2 = 0.f, p3 = 0.f;
#pragma unroll
    for (int q = 0; q < 4; q++) {
        int c = q * 32 + lane;
        float xv = x[(size_t)row * 128 + c];
        p0 += xv * g_v[0][c];
        p1 += xv * g_v[1][c];
        p2 += xv * g_v[2][c];
        p3 += xv * g_v[3][c];
    }
#pragma unroll
    for (int s = 16; s > 0; s >>= 1) {
        p0 += __shfl_xor_sync(0xffffffff, p0, s);
        p1 += __shfl_xor_sync(0xffffffff, p1, s);
        p2 += __shfl_xor_sync(0xffffffff, p2, s);
        p3 += __shfl_xor_sync(0xffffffff, p3, s);
    }
    if (lane == 0) {
        g_s[0][row] = p0 + g_c[0];
        g_s[1][row] = p1 + g_c[1];
        g_s[2][row] = p2 + g_c[2];
        g_s[3][row] = p3 + g_c[3];
    }
}

__global__ void k_m2() {
    int t = threadIdx.x;
    float m0 = -INFINITY, m1 = -INFINITY;
    for (int i = t; i < NR; i += 256) {
        m0 = fmaxf(m0, g_s[1][i]);
        m1 = fmaxf(m1, g_s[3][i]);
    }
    __shared__ float r0[256], r1[256];
    r0[t] = m0; r1[t] = m1;
    __syncthreads();
    for (int s = 128; s > 0; s >>= 1) {
        if (t < s) { r0[t] = fmaxf(r0[t], r0[t + s]); r1[t] = fmaxf(r1[t], r1[t + s]); }
        __syncthreads();
    }
    if (t == 0) { g_M2[0] = r0[0]; g_M2[1] = r1[0]; }
}

__global__ void k_factors() {
    int i = blockIdx.x * 256 + threadIdx.x;
    if (i >= NR) return;
    for (int mz = 0; mz < 2; mz++) {
        float s1 = g_s[2 * mz][i], s2 = g_s[2 * mz + 1][i];
        float a = s1 + g_M2[mz];
        float m = (a >= 0.f) ? a : 0.2f * a;
        g_fA[mz][i] = expf(s1 - m);
        g_fC[mz][i] = expf(0.2f * s1 - m);
        g_fB[mz][i] = expf(s2);
        g_fD[mz][i] = expf(0.2f * s2);
    }
}

// transpose x [4096,128] -> half [128,4096]
__global__ void k_Tx(const float* __restrict__ src, __half* __restrict__ dst) {
    __shared__ float tl[32][129];
    int rb = blockIdx.x * 32, t = threadIdx.x;
    for (int i = t; i < 32 * 128; i += 256) {
        int r = i >> 7, c = i & 127;
        tl[r][c] = src[(size_t)(rb + r) * 128 + c];
    }
    __syncthreads();
    for (int i = t; i < 32 * 128; i += 256) {
        int c = i >> 5, r = i & 31;
        dst[(size_t)c * NRL + rb + r] = __float2half_rn(tl[r][c]);
    }
}

// ---------------- fp16 mma GEMM: slab = A[rows][kslab] @ x[kslab][128] ----------------
#define SM_MMA (5 * TILEW * 4)     // 51200: 2 A bufs + 3 B bufs
__global__ __launch_bounds__(256) void k_mma_big(const float* __restrict__ Ld,
                                                 const float* __restrict__ Lu,
                                                 const float* __restrict__ P) {
    extern __shared__ uint32_t smw[];
    uint32_t smb = smem_u32(smw);
    uint32_t Asb[2] = {smb, smb + TILEW * 4};
    uint32_t Bsb[3] = {smb + 2 * TILEW * 4, smb + 3 * TILEW * 4, smb + 4 * TILEW * 4};

    int tid = threadIdx.x;
    int wid = tid >> 5, lane = tid & 31, gid = lane >> 2, tig = lane & 3;
    int wm = wid >> 1, wn = wid & 1;
    int row = tid >> 1, hb = tid & 1;
    int m8 = lane >> 3, ri = lane & 7;
    uint32_t aoff = (((uint32_t)(m8 & 1) * 8 + ri) * WPR + (m8 >> 1) * 4) * 4;
    uint32_t boff = (((uint32_t)(m8 >> 1) * 8 + ri) * WPR + (m8 & 1) * 4) * 4;

    const float* A = (blockIdx.z == 0) ? Ld : ((blockIdx.z == 1) ? Lu : P);
    float* out = &g_Lx[blockIdx.z][blockIdx.y][0];
    int r0 = blockIdx.x * 128, kb = blockIdx.y * KSLAB;

    size_t arow = (size_t)(r0 + row) * NRL + kb + hb * 16;
    const __half* bsrc = &g_xTh[(size_t)row * NRL + kb + hb * 16];

    float acc[2][8][4];
#pragma unroll
    for (int mi = 0; mi < 2; mi++)
#pragma unroll
        for (int ni = 0; ni < 8; ni++)
#pragma unroll
            for (int q = 0; q < 4; q++) acc[mi][ni][q] = 0.f;

    float4 ar[4];
    auto ldA = [&](int c) {
#pragma unroll
        for (int j = 0; j < 4; j++) ar[j] = *(const float4*)&A[arow + c * 32 + 4 * j];
    };
    auto stA = [&](int s) {
        uint32_t h[8];
#pragma unroll
        for (int j = 0; j < 4; j++) {
            h[2 * j]     = h2u(__floats2half2_rn(ar[j].x, ar[j].y));
            h[2 * j + 1] = h2u(__floats2half2_rn(ar[j].z, ar[j].w));
        }
        uint32_t* d = (uint32_t*)(size_t)0;  // unused; write via smw index
        (void)d;
        uint32_t base = (Asb[s] - smb) / 4 + row * WPR + hb * 8;
        *(uint4*)&smw[base] = make_uint4(h[0], h[1], h[2], h[3]);
        *(uint4*)&smw[base + 4] = make_uint4(h[4], h[5], h[6], h[7]);
    };
    auto cpB = [&](int buf, int c) {
        uint32_t d = Bsb[buf] + (row * WPR + hb * 8) * 4;
        cpasync16(d, bsrc + c * 32);
        cpasync16(d + 16, bsrc + c * 32 + 8);
        CP_COMMIT();
    };
    auto compute = [&](int s, int buf) {
#pragma unroll
        for (int k16 = 0; k16 < 2; k16++) {
            uint32_t a[2][4];
#pragma unroll
            for (int mi = 0; mi < 2; mi++)
                LDSM4(a[mi], Asb[s] + (((wm * 32 + mi * 16) * WPR) + k16 * 8) * 4 + aoff);
#pragma unroll
            for (int nb = 0; nb < 4; nb++) {
                uint32_t b[4];
                LDSM4(b, Bsb[buf] + (((wn * 64 + nb * 16) * WPR) + k16 * 8) * 4 + boff);
                MMA_F16(acc[0][2 * nb], a[0], b[0], b[1]);
                MMA_F16(acc[1][2 * nb], a[1], b[0], b[1]);
                MMA_F16(acc[0][2 * nb + 1], a[0], b[2], b[3]);
                MMA_F16(acc[1][2 * nb + 1], a[1], b[2], b[3]);
            }
        }
    };

    cpB(0, 0);
    cpB(1, 1);
    ldA(0);
    for (int c = 0; c < NCHUNK; c++) {
        int s = c & 1, buf = c % 3;
        if (c + 1 < NCHUNK) { CP_WAIT1(); } else { CP_WAIT0(); }
        __syncthreads();
        if (c + 2 < NCHUNK) cpB((c + 2) % 3, c + 2);
        stA(s);
        if (c + 1 < NCHUNK) ldA(c + 1);
        __syncthreads();
        compute(s, buf);
    }
#pragma unroll
    for (int mi = 0; mi < 2; mi++)
#pragma unroll
        for (int ni = 0; ni < 8; ni++) {
            int orow = r0 + wm * 32 + mi * 16 + gid;
            int ocol = wn * 64 + ni * 8 + 2 * tig;
            *(float2*)&out[(size_t)orow * 128 + ocol] = make_float2(acc[mi][ni][0], acc[mi][ni][1]);
            *(float2*)&out[(size_t)(orow + 8) * 128 + ocol] = make_float2(acc[mi][ni][2], acc[mi][ni][3]);
        }
}

// ---------------- fused masked-softmax attention (num/den slabs) ----------------
#define SM_ATTN (5 * TILEW * 4 + 3 * KSLAB * 4)   // 51200 + 6144
__global__ __launch_bounds__(256) void k_attn(const float* __restrict__ Ld,
                                              const float* __restrict__ Lu) {
    extern __shared__ uint32_t smw[];
    uint32_t smb = smem_u32(smw);
    uint32_t Asb[2] = {smb, smb + TILEW * 4};
    uint32_t Bsb[3] = {smb + 2 * TILEW * 4, smb + 3 * TILEW * 4, smb + 4 * TILEW * 4};
    float* s2c = (float*)(smw + 5 * TILEW);
    float* Bc  = s2c + KSLAB;
    float* Dc  = Bc + KSLAB;

    int tid = threadIdx.x;
    int wid = tid >> 5, lane = tid & 31, gid = lane >> 2, tig = lane & 3;
    int wm = wid >> 1, wn = wid & 1;
    int row = tid >> 1, hb = tid & 1;
    int m8 = lane >> 3, ri = lane & 7;
    uint32_t aoff = (((uint32_t)(m8 & 1) * 8 + ri) * WPR + (m8 >> 1) * 4) * 4;
    uint32_t boff = (((uint32_t)(m8 >> 1) * 8 + ri) * WPR + (m8 & 1) * 4) * 4;

    int mz = blockIdx.z;
    const float* L = mz ? Lu : Ld;
    float* out = &g_num[mz][blockIdx.y][0];
    int i0 = blockIdx.x * 128, kb = blockIdx.y * KSLAB;

    for (int i = tid; i < KSLAB; i += 256) {
        s2c[i] = g_s[2 * mz + 1][kb + i];
        Bc[i]  = g_fB[mz][kb + i];
        Dc[i]  = g_fD[mz][kb + i];
    }
    float s1 = g_s[2 * mz][i0 + row];
    float Ai = g_fA[mz][i0 + row];
    float Ci = g_fC[mz][i0 + row];
    float den_t = 0.f;
    __syncthreads();

    size_t lrow = (size_t)(i0 + row) * NRL + kb + hb * 16;
    const __half* bsrc = &g_MTh[mz][(size_t)row * NRL + kb + hb * 16];

    float acc[2][8][4];
#pragma unroll
    for (int mi = 0; mi < 2; mi++)
#pragma unroll
        for (int ni = 0; ni < 8; ni++)
#pragma unroll
            for (int q = 0; q < 4; q++) acc[mi][ni][q] = 0.f;

    float4 Lr[4];
    auto ldL = [&](int c) {
#pragma unroll
        for (int j = 0; j < 4; j++) Lr[j] = *(const float4*)&L[lrow + c * 32 + 4 * j];
    };
    auto stW = [&](int s, int c) {
        int base = c * 32 + hb * 16;
        uint32_t h[8];
#pragma unroll
        for (int j = 0; j < 4; j++) {
            float4 lv = Lr[j];
            float4 s2v = *(float4*)&s2c[base + 4 * j];
            float4 Bv  = *(float4*)&Bc[base + 4 * j];
            float4 Dv  = *(float4*)&Dc[base + 4 * j];
            float w0 = (lv.x != 0.f) ? ((s1 + s2v.x >= 0.f) ? Ai * Bv.x : Ci * Dv.x) : 0.f;
            float w1 = (lv.y != 0.f) ? ((s1 + s2v.y >= 0.f) ? Ai * Bv.y : Ci * Dv.y) : 0.f;
            float w2 = (lv.z != 0.f) ? ((s1 + s2v.z >= 0.f) ? Ai * Bv.z : Ci * Dv.z) : 0.f;
            float w3 = (lv.w != 0.f) ? ((s1 + s2v.w >= 0.f) ? Ai * Bv.w : Ci * Dv.w) : 0.f;
            __half2 p0 = __floats2half2_rn(w0, w1);
            __half2 p1 = __floats2half2_rn(w2, w3);
            den_t += __low2float(p0) + __high2float(p0) + __low2float(p1) + __high2float(p1);
            h[2 * j] = h2u(p0);
            h[2 * j + 1] = h2u(p1);
        }
        uint32_t base2 = (Asb[s] - smb) / 4 + row * WPR + hb * 8;
        *(uint4*)&smw[base2] = make_uint4(h[0], h[1], h[2], h[3]);
        *(uint4*)&smw[base2 + 4] = make_uint4(h[4], h[5], h[6], h[7]);
    };
    auto cpB = [&](int buf, int c) {
        uint32_t d = Bsb[buf] + (row * WPR + hb * 8) * 4;
        cpasync16(d, bsrc + c * 32);
        cpasync16(d + 16, bsrc + c * 32 + 8);
        CP_COMMIT();
    };
    auto compute = [&](int s, int buf) {
#pragma unroll
        for (int k16 = 0; k16 < 2; k16++) {
            uint32_t a[2][4];
#pragma unroll
            for (int mi = 0; mi < 2; mi++)
                LDSM4(a[mi], Asb[s] + (((wm * 32 + mi * 16) * WPR) + k16 * 8) * 4 + aoff);
#pragma unroll
            for (int nb = 0; nb < 4; nb++) {
                uint32_t b[4];
                LDSM4(b, Bsb[buf] + (((wn * 64 + nb * 16) * WPR) + k16 * 8) * 4 + boff);
                MMA_F16(acc[0][2 * nb], a[0], b[0], b[1]);
                MMA_F16(acc[1][2 * nb], a[1], b[0], b[1]);
                MMA_F16(acc[0][2 * nb + 1], a[0], b[2], b[3]);
                MMA_F16(acc[1][2 * nb + 1], a[1], b[2], b[3]);
            }
        }
    };

    cpB(0, 0);
    cpB(1, 1);
    ldL(0);
    for (int c = 0; c < NCHUNK; c++) {
        int s = c & 1, buf = c % 3;
        if (c + 1 < NCHUNK) { CP_WAIT1(); } else { CP_WAIT0(); }
        __syncthreads();
        if (c + 2 < NCHUNK) cpB((c + 2) % 3, c + 2);
        stW(s, c);
        if (c + 1 < NCHUNK) ldL(c + 1);
        __syncthreads();
        compute(s, buf);
    }
#pragma unroll
    for (int mi = 0; mi < 2; mi++)
#pragma unroll
        for (int ni = 0; ni < 8; ni++) {
            int orow = i0 + wm * 32 + mi * 16 + gid;
            int ocol = wn * 64 + ni * 8 + 2 * tig;
            *(float2*)&out[(size_t)orow * 128 + ocol] = make_float2(acc[mi][ni][0], acc[mi][ni][1]);
            *(float2*)&out[(size_t)(orow + 8) * 128 + ocol] = make_float2(acc[mi][ni][2], acc[mi][ni][3]);
        }
    atomicAdd(&g_den[mz][i0 + row], den_t);
}

// ---------------- epilogue GEMMs (K=128), slab-summing A operands ----------------
template <int NS1, int NS2, bool TRANS_HALF, bool ADD_BIAS>
__global__ __launch_bounds__(256) void k_gemm2(const float* __restrict__ A1, const float* __restrict__ A2,
                                               const float* __restrict__ W1, const float* __restrict__ W2,
                                               float* __restrict__ C, __half* __restrict__ CT) {
    __shared__ float A1s[32][33];
    __shared__ float A2s[32][33];
    __shared__ float W1s[32][128];
    __shared__ float W2s[32][128];
    __shared__ __half stg[32][136];
    int tid = threadIdx.x;
    int bm = blockIdx.x * 32;
    int trow = (tid >> 5) * 4;
    int tcol = (tid & 31) * 4;
    int am = tid >> 3;
    int ak = (tid & 7) * 4;
    int wr = tid >> 5;
    int wc = (tid & 31) * 4;
    float acc[4][4];
#pragma unroll
    for (int r = 0; r < 4; r++)
#pragma unroll
        for (int c = 0; c < 4; c++) acc[r][c] = 0.f;

    for (int kk = 0; kk < 128; kk += 32) {
        size_t aidx = (size_t)(bm + am) * 128 + kk + ak;
        float4 a1 = *(const float4*)&A1[aidx];
#pragma unroll
        for (int p = 1; p < NS1; p++) {
            float4 t = *(const float4*)&A1[p * SLAB + aidx];
            a1.x += t.x; a1.y += t.y; a1.z += t.z; a1.w += t.w;
        }
        A1s[ak + 0][am] = a1.x; A1s[ak + 1][am] = a1.y; A1s[ak + 2][am] = a1.z; A1s[ak + 3][am] = a1.w;
        if (NS2 > 0) {
            float4 a2 = *(const float4*)&A2[aidx];
#pragma unroll
            for (int p = 1; p < NS2; p++) {
                float4 t = *(const float4*)&A2[p * SLAB + aidx];
                a2.x += t.x; a2.y += t.y; a2.z += t.z; a2.w += t.w;
            }
            A2s[ak + 0][am] = a2.x; A2s[ak + 1][am] = a2.y; A2s[ak + 2][am] = a2.z; A2s[ak + 3][am] = a2.w;
        }
#pragma unroll
        for (int q = 0; q < 4; q++) {
            *(float4*)&W1s[wr + q * 8][wc] = *(const float4*)&W1[(size_t)(kk + wr + q * 8) * 128 + wc];
            if (NS2 > 0)
                *(float4*)&W2s[wr + q * 8][wc] = *(const float4*)&W2[(size_t)(kk + wr + q * 8) * 128 + wc];
        }
        __syncthreads();
#pragma unroll
        for (int k = 0; k < 32; k++) {
            float a1f[4], a2f[4];
#pragma unroll
            for (int r = 0; r < 4; r++) {
                a1f[r] = A1s[k][trow + r];
                if (NS2 > 0) a2f[r] = A2s[k][trow + r];
            }
            float4 w1v = *(float4*)&W1s[k][tcol];
            float4 w2v;
            if (NS2 > 0) w2v = *(float4*)&W2s[k][tcol];
#pragma unroll
            for (int r = 0; r < 4; r++) {
                acc[r][0] += a1f[r] * w1v.x;
                acc[r][1] += a1f[r] * w1v.y;
                acc[r][2] += a1f[r] * w1v.z;
                acc[r][3] += a1f[r] * w1v.w;
                if (NS2 > 0) {
                    acc[r][0] += a2f[r] * w2v.x;
                    acc[r][1] += a2f[r] * w2v.y;
                    acc[r][2] += a2f[r] * w2v.z;
                    acc[r][3] += a2f[r] * w2v.w;
                }
            }
        }
        __syncthreads();
    }
    if (TRANS_HALF) {
#pragma unroll
        for (int r = 0; r < 4; r++)
#pragma unroll
            for (int c = 0; c < 4; c++)
                stg[trow + r][tcol + c] = __float2half_rn(acc[r][c]);
        __syncthreads();
        int col = tid >> 1, r0 = (tid & 1) * 16;
        __half hv[16];
#pragma unroll
        for (int j = 0; j < 16; j++) hv[j] = stg[r0 + j][col];
        *(uint4*)&CT[(size_t)col * NRL + bm + r0] = *(uint4*)&hv[0];
        *(uint4*)&CT[(size_t)col * NRL + bm + r0 + 8] = *(uint4*)&hv[8];
    } else {
#pragma unroll
        for (int r = 0; r < 4; r++) {
            float4 o = make_float4(acc[r][0], acc[r][1], acc[r][2], acc[r][3]);
            if (ADD_BIAS) {
                o.x += g_bias[tcol + 0];
                o.y += g_bias[tcol + 1];
                o.z += g_bias[tcol + 2];
                o.w += g_bias[tcol + 3];
            }
            *(float4*)&C[(size_t)(bm + trow + r) * 128 + tcol] = o;
        }
    }
}

__global__ void k_final(float* __restrict__ z) {
    int idx = blockIdx.x * 256 + threadIdx.x;
    int i = idx >> 7;
    float d0 = g_den[0][i]; if (!(d0 > 0.f)) d0 = 1.f;
    float d1 = g_den[1][i]; if (!(d1 > 0.f)) d1 = 1.f;
    float n0 = 0.f, n1 = 0.f;
#pragma unroll
    for (int p = 0; p < KSPLIT; p++) {
        n0 += g_num[0][p][idx];
        n1 += g_num[1][p][idx];
    }
    z[idx] += n0 / d0 + n1 / d1;
}

// ---------------- host launcher ----------------
extern "C" void kernel_launch(void* const* d_in, const int* in_sizes, int n_in,
                              void* d_out, int out_size) {
    const float* x       = (const float*)d_in[0];
    const float* Lu      = (const float*)d_in[1];
    const float* Ld      = (const float*)d_in[2];
    const float* P       = (const float*)d_in[3];
    const float* Wi_w    = (const float*)d_in[4];
    const float* Wi_b    = (const float*)d_in[5];
    const float* Ws_w    = (const float*)d_in[6];
    const float* Ws_b    = (const float*)d_in[7];
    const float* Wh_w    = (const float*)d_in[8];
    const float* Wh_b    = (const float*)d_in[9];
    const float* att_irr = (const float*)d_in[10];
    const float* att_sol = (const float*)d_in[11];
    float* z = (float*)d_out;

    cudaFuncSetAttribute((const void*)k_mma_big, cudaFuncAttributeMaxDynamicSharedMemorySize, SM_MMA);
    cudaFuncSetAttribute((const void*)k_attn, cudaFuncAttributeMaxDynamicSharedMemorySize, SM_ATTN);

    float *p_Lx, *p_den;
    __half *p_xTh, *p_MTh;
    cudaGetSymbolAddress((void**)&p_Lx, g_Lx);
    cudaGetSymbolAddress((void**)&p_den, g_den);
    cudaGetSymbolAddress((void**)&p_xTh, g_xTh);
    cudaGetSymbolAddress((void**)&p_MTh, g_MTh);
    const float* p_Ldx = p_Lx;                       // [KSPLIT][SLAB]
    const float* p_Lux = p_Lx + (size_t)KSPLIT * SLAB;
    const float* p_Px  = p_Lx + (size_t)2 * KSPLIT * SLAB;

    cudaMemsetAsync(p_den, 0, 2 * NR * sizeof(float));

    k_prep<<<1, 128>>>(Wi_w, Wi_b, Ws_w, Ws_b, Wh_b, att_irr, att_sol);
    k_scores<<<NR / 8, 256>>>(x);
    k_m2<<<1, 256>>>();
    k_factors<<<NR / 256, 256>>>();
    k_Tx<<<NR / 32, 256>>>(x, p_xTh);

    k_mma_big<<<dim3(NR / 128, KSPLIT, 3), 256, SM_MMA>>>(Ld, Lu, P);

    // MT_irr = (x@Wi0 + (Σ Ldx slabs)@Wi1)^T (half); MT_sol likewise; z = (Σ Px slabs)@Wh + bias
    k_gemm2<1, KSPLIT, true, false><<<NR / 32, 256>>>(x, p_Ldx, Wi_w, Wi_w + 128 * 128, nullptr, p_MTh);
    k_gemm2<1, KSPLIT, true, false><<<NR / 32, 256>>>(x, p_Lux, Ws_w, Ws_w + 128 * 128, nullptr, p_MTh + 128 * NRL);
    k_gemm2<KSPLIT, 0, false, true><<<NR / 32, 256>>>(p_Px, nullptr, Wh_w, nullptr, z, nullptr);

    k_attn<<<dim3(NR / 128, KSPLIT, 2), 256, SM_ATTN>>>(Ld, Lu);
    k_final<<<NR * 128 / 256, 256>>>(z);
}